// round 2
// baseline (speedup 1.0000x reference)
#include <cuda_runtime.h>
#include <math.h>

// Problem constants
#define BB 16
#define NN 4096
#define SS 1024
#define KK 32
#define M_ROWS (BB*SS*KK)      // 524288 rows (b,s,k)
#define OUT_XYZ_ELEMS (BB*SS*3)  // 49152

// ---------------- scratch (__device__ globals; no allocation allowed) -------
__device__ float  g_y1[M_ROWS*64];      // layer1 pre-BN output
__device__ float  g_y2[M_ROWS*64];      // layer2 pre-BN output
__device__ float  g_mx[BB*SS*128];      // layer3 pre-BN max over k
__device__ float  g_mn[BB*SS*128];      // layer3 pre-BN min over k
__device__ int    g_ball[M_ROWS];       // ball query indices
__device__ double g_sum1[64],  g_sq1[64];
__device__ double g_sum2[64],  g_sq2[64];
__device__ double g_sum3[128], g_sq3[128];
__device__ float  g_a1[64], g_c1[64];
__device__ float  g_a2[64], g_c2[64];
__device__ float  g_a3[128], g_c3[128];

// ---------------- init: zero stat accumulators ------------------------------
__global__ void k_init() {
    int t = threadIdx.x;
    if (t < 64)  { g_sum1[t]=0.0; g_sq1[t]=0.0; g_sum2[t]=0.0; g_sq2[t]=0.0; }
    if (t < 128) { g_sum3[t]=0.0; g_sq3[t]=0.0; }
}

// ---------------- FPS: one block per batch, register-resident ---------------
// Matches the jax scan exactly: record far; dist=min(dist,d(centroid=far));
// far=argmax(dist) with FIRST-index tie-break. Distances computed with
// uncontracted mul/add to match XLA elementwise codegen bit-for-bit.
// Each thread owns 8 points (i = tid + j*512) entirely in registers; the
// owner thread of `far` broadcasts the centroid through 3 smem floats.
__global__ __launch_bounds__(512) void k_fps(const float* __restrict__ xyz,
                                             float* __restrict__ newxyz) {
    __shared__ float scen[3];
    __shared__ float srv[16];
    __shared__ int   sri[16];
    __shared__ int   sfar;
    const int b = blockIdx.x, tid = threadIdx.x;
    const float* base = xyz + (size_t)b*NN*3;
    float px[8], py[8], pz[8], dist[8];
#pragma unroll
    for (int j = 0; j < 8; j++) {
        const int i = tid + (j << 9);
        px[j] = base[3*i+0]; py[j] = base[3*i+1]; pz[j] = base[3*i+2];
        dist[j] = 1e10f;
    }

    int far = 0;
    float* outc = newxyz + (size_t)b*SS*3;
    const int lane = tid & 31, w = tid >> 5;
    for (int it = 0; it < SS; it++) {
        const int ow = far & 511, oj = far >> 9;
        if (tid == ow) {
            scen[0] = px[oj]; scen[1] = py[oj]; scen[2] = pz[oj];
            outc[3*it+0] = px[oj]; outc[3*it+1] = py[oj]; outc[3*it+2] = pz[oj];
        }
        __syncthreads();
        const float cx = scen[0], cy = scen[1], cz = scen[2];
        float bv = -1.0f; int bi = 0x7fffffff;
#pragma unroll
        for (int j = 0; j < 8; j++) {
            float dx = px[j] - cx, dy = py[j] - cy, dz = pz[j] - cz;
            float d = __fadd_rn(__fadd_rn(__fmul_rn(dx,dx), __fmul_rn(dy,dy)),
                                __fmul_rn(dz,dz));
            float dd = fminf(dist[j], d);
            dist[j] = dd;
            if (dd > bv) { bv = dd; bi = tid + (j << 9); } // j asc -> first-index on tie per thread
        }
#pragma unroll
        for (int off = 16; off; off >>= 1) {
            float ov = __shfl_down_sync(0xffffffffu, bv, off);
            int   oi = __shfl_down_sync(0xffffffffu, bi, off);
            if (ov > bv || (ov == bv && oi < bi)) { bv = ov; bi = oi; }
        }
        if (lane == 0) { srv[w] = bv; sri[w] = bi; }
        __syncthreads();
        if (tid < 32) {
            bv = (tid < 16) ? srv[tid] : -1.0f;
            bi = (tid < 16) ? sri[tid] : 0x7fffffff;
#pragma unroll
            for (int off = 8; off; off >>= 1) {
                float ov = __shfl_down_sync(0xffffffffu, bv, off);
                int   oi = __shfl_down_sync(0xffffffffu, bi, off);
                if (ov > bv || (ov == bv && oi < bi)) { bv = ov; bi = oi; }
            }
            if (tid == 0) sfar = bi;
        }
        __syncthreads();
        far = sfar;
    }
}

// ---------------- ball query: first 32 indices (ascending) within radius ----
__global__ __launch_bounds__(256) void k_ball(const float* __restrict__ xyz,
                                              const float* __restrict__ newxyz) {
    extern __shared__ float sm[];
    float* sx = sm; float* sy = sm + NN; float* sz = sm + 2*NN;
    const int b = blockIdx.y;
    const float* base = xyz + (size_t)b*NN*3;
    for (int i = threadIdx.x; i < NN; i += 256) {
        sx[i] = base[3*i+0]; sy[i] = base[3*i+1]; sz[i] = base[3*i+2];
    }
    __syncthreads();
    const int wid = threadIdx.x >> 5, lane = threadIdx.x & 31;
    const int s = blockIdx.x * 8 + wid;
    const int g = b * SS + s;
    const float cx = newxyz[3*g+0], cy = newxyz[3*g+1], cz = newxyz[3*g+2];
    int* out = g_ball + (size_t)g*KK;
    int count = 0, first = -1;
    for (int j0 = 0; j0 < NN && count < KK; j0 += 32) {
        const int j = j0 + lane;
        float dx = sx[j]-cx, dy = sy[j]-cy, dz = sz[j]-cz;
        float d = __fadd_rn(__fadd_rn(__fmul_rn(dx,dx), __fmul_rn(dy,dy)),
                            __fmul_rn(dz,dz));
        const bool in = !(d > 0.04f);   // same predicate as reference (exclude if > r^2)
        unsigned m = __ballot_sync(0xffffffffu, in);
        if (first < 0 && m) first = j0 + __ffs(m) - 1;
        int pre = __popc(m & ((1u << lane) - 1u));
        if (in) { int p = count + pre; if (p < KK) out[p] = j; }
        count += __popc(m);
    }
    if (count < KK) {
        for (int t = count + lane; t < KK; t += 32) out[t] = first;
    }
}

// ---------------- layer 1: gather+concat(35) -> 64, + BN stats --------------
__global__ __launch_bounds__(128) void k_layer1(const float* __restrict__ xyz,
                                                const float* __restrict__ points,
                                                const float* __restrict__ newxyz,
                                                const float* __restrict__ w,
                                                const float* __restrict__ bias) {
    __shared__ float sX[64*35];
    __shared__ float sW[35*64];     // transposed: sW[i*64+o]
    __shared__ float sred[8][64];
    __shared__ int   sidx[64];
    __shared__ float scen[6];
    __shared__ float sb[64];
    const int tid = threadIdx.x;
    const int row0 = blockIdx.x * 64;
    const int b = row0 >> 15;          // 32768 rows per batch
    const int grp0 = row0 >> 5;        // global (b*S+s) group of first row
    if (tid < 64) { sidx[tid] = g_ball[row0 + tid]; sb[tid] = bias[tid]; }
    if (tid < 6)  scen[tid] = newxyz[grp0*3 + tid];   // two consecutive centers
    for (int e = tid; e < 35*64; e += 128) {
        int o = e / 35, i = e - o*35;
        sW[i*64 + o] = w[e];
    }
    __syncthreads();
    for (int e = tid; e < 64*35; e += 128) {
        int r = e / 35, i = e - r*35;
        int pidx = sidx[r];
        float v;
        if (i < 3) v = xyz[((size_t)b*NN + pidx)*3 + i] - scen[(r >> 5)*3 + i];
        else       v = points[((size_t)b*NN + pidx)*32 + (i - 3)];
        sX[r*35 + i] = v;
    }
    __syncthreads();
    const int tx = tid & 15, ty = tid >> 4;
    float acc[4][8];
#pragma unroll
    for (int c = 0; c < 4; c++) {
        float bv = sb[tx + 16*c];
#pragma unroll
        for (int j = 0; j < 8; j++) acc[c][j] = bv;
    }
    for (int i = 0; i < 35; i++) {
        float wv[4];
#pragma unroll
        for (int c = 0; c < 4; c++) wv[c] = sW[i*64 + tx + 16*c];
#pragma unroll
        for (int j = 0; j < 8; j++) {
            float xv = sX[(ty + 8*j)*35 + i];
#pragma unroll
            for (int c = 0; c < 4; c++) acc[c][j] = fmaf(wv[c], xv, acc[c][j]);
        }
    }
    float ls[4] = {0,0,0,0}, lq[4] = {0,0,0,0};
#pragma unroll
    for (int c = 0; c < 4; c++) {
        const int ch = tx + 16*c;
#pragma unroll
        for (int j = 0; j < 8; j++) {
            const int r = ty + 8*j;
            float y = acc[c][j];
            g_y1[(size_t)(row0 + r)*64 + ch] = y;
            ls[c] += y; lq[c] += y*y;
        }
    }
#pragma unroll
    for (int c = 0; c < 4; c++) sred[ty][tx + 16*c] = ls[c];
    __syncthreads();
    if (tid < 64) {
        float t = 0.f;
#pragma unroll
        for (int yy = 0; yy < 8; yy++) t += sred[yy][tid];
        atomicAdd(&g_sum1[tid], (double)t);
    }
    __syncthreads();
#pragma unroll
    for (int c = 0; c < 4; c++) sred[ty][tx + 16*c] = lq[c];
    __syncthreads();
    if (tid < 64) {
        float t = 0.f;
#pragma unroll
        for (int yy = 0; yy < 8; yy++) t += sred[yy][tid];
        atomicAdd(&g_sq1[tid], (double)t);
    }
}

// ---------------- layer 2: BN1+ReLU(64) -> 64, + BN stats -------------------
__global__ __launch_bounds__(128) void k_layer2(const float* __restrict__ w,
                                                const float* __restrict__ bias) {
    __shared__ float sX[64*65];
    __shared__ float sW[64*64];     // transposed
    __shared__ float sred[8][64];
    __shared__ float sa[64], sc[64], sb[64];
    const int tid = threadIdx.x;
    const int row0 = blockIdx.x * 64;
    if (tid < 64) { sa[tid] = g_a1[tid]; sc[tid] = g_c1[tid]; sb[tid] = bias[tid]; }
    for (int e = tid; e < 64*64; e += 128) {
        int o = e >> 6, i = e & 63;
        sW[i*64 + o] = w[e];
    }
    __syncthreads();
    for (int e = tid; e < 64*64; e += 128) {
        int r = e >> 6, i = e & 63;
        float v = g_y1[(size_t)(row0 + r)*64 + i];
        v = fmaxf(fmaf(sa[i], v, sc[i]), 0.f);
        sX[r*65 + i] = v;
    }
    __syncthreads();
    const int tx = tid & 15, ty = tid >> 4;
    float acc[4][8];
#pragma unroll
    for (int c = 0; c < 4; c++) {
        float bv = sb[tx + 16*c];
#pragma unroll
        for (int j = 0; j < 8; j++) acc[c][j] = bv;
    }
    for (int i = 0; i < 64; i++) {
        float wv[4];
#pragma unroll
        for (int c = 0; c < 4; c++) wv[c] = sW[i*64 + tx + 16*c];
#pragma unroll
        for (int j = 0; j < 8; j++) {
            float xv = sX[(ty + 8*j)*65 + i];
#pragma unroll
            for (int c = 0; c < 4; c++) acc[c][j] = fmaf(wv[c], xv, acc[c][j]);
        }
    }
    float ls[4] = {0,0,0,0}, lq[4] = {0,0,0,0};
#pragma unroll
    for (int c = 0; c < 4; c++) {
        const int ch = tx + 16*c;
#pragma unroll
        for (int j = 0; j < 8; j++) {
            const int r = ty + 8*j;
            float y = acc[c][j];
            g_y2[(size_t)(row0 + r)*64 + ch] = y;
            ls[c] += y; lq[c] += y*y;
        }
    }
#pragma unroll
    for (int c = 0; c < 4; c++) sred[ty][tx + 16*c] = ls[c];
    __syncthreads();
    if (tid < 64) {
        float t = 0.f;
#pragma unroll
        for (int yy = 0; yy < 8; yy++) t += sred[yy][tid];
        atomicAdd(&g_sum2[tid], (double)t);
    }
    __syncthreads();
#pragma unroll
    for (int c = 0; c < 4; c++) sred[ty][tx + 16*c] = lq[c];
    __syncthreads();
    if (tid < 64) {
        float t = 0.f;
#pragma unroll
        for (int yy = 0; yy < 8; yy++) t += sred[yy][tid];
        atomicAdd(&g_sq2[tid], (double)t);
    }
}

// ---------------- layer 3: BN2+ReLU(64) -> 128, stats + max/min over k ------
// One block == one (b,s) group of 32 rows. y3 never stored; only max/min.
__global__ __launch_bounds__(128) void k_layer3(const float* __restrict__ w,
                                                const float* __restrict__ bias) {
    __shared__ float sX[32*65];
    __shared__ float sW[64*128];    // transposed
    __shared__ float sred[4][128];
    __shared__ float sa[64], sc[64], sb[128];
    const int tid = threadIdx.x;
    const int grp = blockIdx.x;
    const int row0 = grp * 32;
    if (tid < 64)  { sa[tid] = g_a2[tid]; sc[tid] = g_c2[tid]; }
    if (tid < 128) sb[tid] = bias[tid];
    for (int e = tid; e < 64*128; e += 128) {
        int o = e >> 6, i = e & 63;
        sW[i*128 + o] = w[e];
    }
    __syncthreads();
    for (int e = tid; e < 32*64; e += 128) {
        int r = e >> 6, i = e & 63;
        float v = g_y2[(size_t)(row0 + r)*64 + i];
        v = fmaxf(fmaf(sa[i], v, sc[i]), 0.f);
        sX[r*65 + i] = v;
    }
    __syncthreads();
    const int tx = tid & 31, ty = tid >> 5;   // 32 ch-groups x 4 row-groups
    float acc[4][8];
#pragma unroll
    for (int c = 0; c < 4; c++) {
        float bv = sb[tx + 32*c];
#pragma unroll
        for (int j = 0; j < 8; j++) acc[c][j] = bv;
    }
    for (int i = 0; i < 64; i++) {
        float wv[4];
#pragma unroll
        for (int c = 0; c < 4; c++) wv[c] = sW[i*128 + tx + 32*c];
#pragma unroll
        for (int j = 0; j < 8; j++) {
            float xv = sX[(ty + 4*j)*65 + i];
#pragma unroll
            for (int c = 0; c < 4; c++) acc[c][j] = fmaf(wv[c], xv, acc[c][j]);
        }
    }
    float ls[4] = {0,0,0,0}, lq[4] = {0,0,0,0};
    float lx[4] = {-1e30f,-1e30f,-1e30f,-1e30f};
    float ln[4] = { 1e30f, 1e30f, 1e30f, 1e30f};
#pragma unroll
    for (int c = 0; c < 4; c++)
#pragma unroll
        for (int j = 0; j < 8; j++) {
            float y = acc[c][j];
            ls[c] += y; lq[c] += y*y;
            lx[c] = fmaxf(lx[c], y); ln[c] = fminf(ln[c], y);
        }
    // 4 reduction phases over ty (sum, sq, max, min)
#pragma unroll
    for (int c = 0; c < 4; c++) sred[ty][tx + 32*c] = ls[c];
    __syncthreads();
    if (tid < 128) {
        float t = sred[0][tid] + sred[1][tid] + sred[2][tid] + sred[3][tid];
        atomicAdd(&g_sum3[tid], (double)t);
    }
    __syncthreads();
#pragma unroll
    for (int c = 0; c < 4; c++) sred[ty][tx + 32*c] = lq[c];
    __syncthreads();
    if (tid < 128) {
        float t = sred[0][tid] + sred[1][tid] + sred[2][tid] + sred[3][tid];
        atomicAdd(&g_sq3[tid], (double)t);
    }
    __syncthreads();
#pragma unroll
    for (int c = 0; c < 4; c++) sred[ty][tx + 32*c] = lx[c];
    __syncthreads();
    if (tid < 128) {
        float t = fmaxf(fmaxf(sred[0][tid], sred[1][tid]),
                        fmaxf(sred[2][tid], sred[3][tid]));
        g_mx[(size_t)grp*128 + tid] = t;
    }
    __syncthreads();
#pragma unroll
    for (int c = 0; c < 4; c++) sred[ty][tx + 32*c] = ln[c];
    __syncthreads();
    if (tid < 128) {
        float t = fminf(fminf(sred[0][tid], sred[1][tid]),
                        fminf(sred[2][tid], sred[3][tid]));
        g_mn[(size_t)grp*128 + tid] = t;
    }
}

// ---------------- BN parameter derivation (per layer) -----------------------
__global__ void k_bn(int layer, const float* __restrict__ gg,
                     const float* __restrict__ be, int n) {
    int i = threadIdx.x;
    if (i >= n) return;
    const double* sum; const double* sq; float* a; float* c;
    if (layer == 0)      { sum = g_sum1; sq = g_sq1; a = g_a1; c = g_c1; }
    else if (layer == 1) { sum = g_sum2; sq = g_sq2; a = g_a2; c = g_c2; }
    else                 { sum = g_sum3; sq = g_sq3; a = g_a3; c = g_c3; }
    const double invM = 1.0 / (double)M_ROWS;
    double mean = sum[i] * invM;
    double var  = sq[i] * invM - mean * mean;
    double A = (double)gg[i] / sqrt(var + 1e-5);
    a[i] = (float)A;
    c[i] = (float)((double)be[i] - A * mean);
}

// ---------------- final: BN3 affine + ReLU on max/min, write output ---------
__global__ __launch_bounds__(256) void k_final(float* __restrict__ out) {
    int gid = blockIdx.x * 256 + threadIdx.x;     // over B*128*S
    int s  = gid & 1023;
    int ch = (gid >> 10) & 127;
    int b  = gid >> 17;
    float A = g_a3[ch], C = g_c3[ch];
    size_t gi = ((size_t)((b << 10) | s))*128 + ch;
    float m = (A >= 0.f) ? g_mx[gi] : g_mn[gi];
    out[OUT_XYZ_ELEMS + gid] = fmaxf(fmaf(A, m, C), 0.f);
}

// ---------------- launch ----------------------------------------------------
extern "C" void kernel_launch(void* const* d_in, const int* in_sizes, int n_in,
                              void* d_out, int out_size) {
    const float* xyz    = (const float*)d_in[0];
    const float* points = (const float*)d_in[1];
    const float* w0  = (const float*)d_in[2];
    const float* b0  = (const float*)d_in[3];
    const float* g0  = (const float*)d_in[4];
    const float* be0 = (const float*)d_in[5];
    const float* w1  = (const float*)d_in[6];
    const float* b1  = (const float*)d_in[7];
    const float* g1  = (const float*)d_in[8];
    const float* be1 = (const float*)d_in[9];
    const float* w2  = (const float*)d_in[10];
    const float* b2  = (const float*)d_in[11];
    const float* g2  = (const float*)d_in[12];
    const float* be2 = (const float*)d_in[13];
    float* out = (float*)d_out;
    (void)in_sizes; (void)n_in; (void)out_size;

    const size_t smem_xyz = (size_t)3 * NN * sizeof(float);   // 48KB dynamic, no statics

    k_init<<<1, 128>>>();
    k_fps<<<BB, 512>>>(xyz, out);
    k_ball<<<dim3(128, BB), 256, smem_xyz>>>(xyz, out);
    k_layer1<<<M_ROWS/64, 128>>>(xyz, points, out, w0, b0);
    k_bn<<<1, 128>>>(0, g0, be0, 64);
    k_layer2<<<M_ROWS/64, 128>>>(w1, b1);
    k_bn<<<1, 128>>>(1, g1, be1, 64);
    k_layer3<<<M_ROWS/32, 128>>>(w2, b2);
    k_bn<<<1, 128>>>(2, g2, be2, 128);
    k_final<<<(BB*128*SS)/256, 256>>>(out);
}

// round 3
// speedup vs baseline: 1.1056x; 1.1056x over previous
#include <cuda_runtime.h>
#include <math.h>

// Problem constants
#define BB 16
#define NN 4096
#define SS 1024
#define KK 32
#define M_ROWS (BB*SS*KK)        // 524288 rows (b,s,k)
#define OUT_XYZ_ELEMS (BB*SS*3)  // 49152

#define RS1 40   // layer1 X row stride (36 used)
#define RS2 68   // layer2/3 X row stride (64 used)

// ---------------- scratch (__device__ globals) ------------------------------
__device__ float  g_y1[M_ROWS*64];
__device__ float  g_y2[M_ROWS*64];
__device__ float  g_mx[BB*SS*128];
__device__ float  g_mn[BB*SS*128];
__device__ int    g_ball[M_ROWS];
__device__ double g_sum1[64],  g_sq1[64];
__device__ double g_sum2[64],  g_sq2[64];
__device__ double g_sum3[128], g_sq3[128];
__device__ float  g_a1[64], g_c1[64];
__device__ float  g_a2[64], g_c2[64];
__device__ float  g_a3[128], g_c3[128];

// ---------------- init ------------------------------------------------------
__global__ void k_init() {
    int t = threadIdx.x;
    if (t < 64)  { g_sum1[t]=0.0; g_sq1[t]=0.0; g_sum2[t]=0.0; g_sq2[t]=0.0; }
    if (t < 128) { g_sum3[t]=0.0; g_sq3[t]=0.0; }
}

// ---------------- FPS: register-resident, coord-carrying argmax -------------
// No dynamic register-array indexing anywhere -> px/py/pz/dist stay in regs.
// 2 barriers/iter. First-index tie-break; uncontracted distance math.
__global__ __launch_bounds__(512) void k_fps(const float* __restrict__ xyz,
                                             float* __restrict__ newxyz) {
    __shared__ float srv[16], srx[16], sry[16], srz[16];
    __shared__ int   sri[16];
    __shared__ float scen[3];
    const int b = blockIdx.x, tid = threadIdx.x;
    const float* base = xyz + (size_t)b*NN*3;
    float px[8], py[8], pz[8], dist[8];
#pragma unroll
    for (int j = 0; j < 8; j++) {
        const int i = tid + (j << 9);
        px[j] = base[3*i+0]; py[j] = base[3*i+1]; pz[j] = base[3*i+2];
        dist[j] = 1e10f;
    }
    float* outc = newxyz + (size_t)b*SS*3;
    if (tid == 0) {
        scen[0] = px[0]; scen[1] = py[0]; scen[2] = pz[0];
        outc[0] = px[0]; outc[1] = py[0]; outc[2] = pz[0];
    }
    __syncthreads();
    const int lane = tid & 31, w = tid >> 5;
    for (int it = 0; it < SS; it++) {
        const float cx = scen[0], cy = scen[1], cz = scen[2];
        float bv = -1.0f, bx = 0.f, by = 0.f, bz = 0.f;
        int bi = 0x7fffffff;
#pragma unroll
        for (int j = 0; j < 8; j++) {
            float dx = px[j] - cx, dy = py[j] - cy, dz = pz[j] - cz;
            float d = __fadd_rn(__fadd_rn(__fmul_rn(dx,dx), __fmul_rn(dy,dy)),
                                __fmul_rn(dz,dz));
            float dd = fminf(dist[j], d);
            dist[j] = dd;
            if (dd > bv) { bv = dd; bi = tid + (j << 9); bx = px[j]; by = py[j]; bz = pz[j]; }
        }
#pragma unroll
        for (int off = 16; off; off >>= 1) {
            float ov = __shfl_down_sync(0xffffffffu, bv, off);
            int   oi = __shfl_down_sync(0xffffffffu, bi, off);
            float ox = __shfl_down_sync(0xffffffffu, bx, off);
            float oy = __shfl_down_sync(0xffffffffu, by, off);
            float oz = __shfl_down_sync(0xffffffffu, bz, off);
            if (ov > bv || (ov == bv && oi < bi)) { bv=ov; bi=oi; bx=ox; by=oy; bz=oz; }
        }
        if (lane == 0) { srv[w]=bv; sri[w]=bi; srx[w]=bx; sry[w]=by; srz[w]=bz; }
        __syncthreads();
        if (tid < 32) {
            bv = (tid < 16) ? srv[tid] : -1.0f;
            bi = (tid < 16) ? sri[tid] : 0x7fffffff;
            bx = (tid < 16) ? srx[tid] : 0.f;
            by = (tid < 16) ? sry[tid] : 0.f;
            bz = (tid < 16) ? srz[tid] : 0.f;
#pragma unroll
            for (int off = 8; off; off >>= 1) {
                float ov = __shfl_down_sync(0xffffffffu, bv, off);
                int   oi = __shfl_down_sync(0xffffffffu, bi, off);
                float ox = __shfl_down_sync(0xffffffffu, bx, off);
                float oy = __shfl_down_sync(0xffffffffu, by, off);
                float oz = __shfl_down_sync(0xffffffffu, bz, off);
                if (ov > bv || (ov == bv && oi < bi)) { bv=ov; bi=oi; bx=ox; by=oy; bz=oz; }
            }
            if (tid == 0) {
                scen[0] = bx; scen[1] = by; scen[2] = bz;
                if (it < SS-1) {
                    outc[3*(it+1)+0] = bx; outc[3*(it+1)+1] = by; outc[3*(it+1)+2] = bz;
                }
            }
        }
        __syncthreads();
    }
}

// ---------------- ball query ------------------------------------------------
__global__ __launch_bounds__(256) void k_ball(const float* __restrict__ xyz,
                                              const float* __restrict__ newxyz) {
    extern __shared__ float sm[];
    float* sx = sm; float* sy = sm + NN; float* sz = sm + 2*NN;
    const int b = blockIdx.y;
    const float* base = xyz + (size_t)b*NN*3;
    for (int i = threadIdx.x; i < NN; i += 256) {
        sx[i] = base[3*i+0]; sy[i] = base[3*i+1]; sz[i] = base[3*i+2];
    }
    __syncthreads();
    const int wid = threadIdx.x >> 5, lane = threadIdx.x & 31;
    const int s = blockIdx.x * 8 + wid;
    const int g = b * SS + s;
    const float cx = newxyz[3*g+0], cy = newxyz[3*g+1], cz = newxyz[3*g+2];
    int* out = g_ball + (size_t)g*KK;
    int count = 0, first = -1;
    for (int j0 = 0; j0 < NN && count < KK; j0 += 32) {
        const int j = j0 + lane;
        float dx = sx[j]-cx, dy = sy[j]-cy, dz = sz[j]-cz;
        float d = __fadd_rn(__fadd_rn(__fmul_rn(dx,dx), __fmul_rn(dy,dy)),
                            __fmul_rn(dz,dz));
        const bool in = !(d > 0.04f);
        unsigned m = __ballot_sync(0xffffffffu, in);
        if (first < 0 && m) first = j0 + __ffs(m) - 1;
        int pre = __popc(m & ((1u << lane) - 1u));
        if (in) { int p = count + pre; if (p < KK) out[p] = j; }
        count += __popc(m);
    }
    if (count < KK) {
        for (int t = count + lane; t < KK; t += 32) out[t] = first;
    }
}

// FMA helper: acc[c][j] += W4 component-c * xs
#define FMA4(W4, xs, j) \
    acc[0][j] = fmaf((W4).x, (xs), acc[0][j]); \
    acc[1][j] = fmaf((W4).y, (xs), acc[1][j]); \
    acc[2][j] = fmaf((W4).z, (xs), acc[2][j]); \
    acc[3][j] = fmaf((W4).w, (xs), acc[3][j]);

// ---------------- layer 1: gather+concat(36 padded) -> 64 -------------------
// Channel order inside the GEMM: [points(32), xyz-center(3), pad(1)].
__global__ __launch_bounds__(128) void k_layer1(const float* __restrict__ xyz,
                                                const float* __restrict__ points,
                                                const float* __restrict__ newxyz,
                                                const float* __restrict__ w,
                                                const float* __restrict__ bias) {
    __shared__ __align__(16) float sX[64*RS1];
    __shared__ __align__(16) float sWT[36*64];
    __shared__ __align__(16) float sred[8][64];
    __shared__ int   sidx[64];
    __shared__ float scen[8];
    __shared__ float sb[64];
    const int tid = threadIdx.x;
    const int row0 = blockIdx.x * 64;
    const int b = row0 >> 15;
    const int grp0 = row0 >> 5;
    if (tid < 64) { sidx[tid] = g_ball[row0 + tid]; sb[tid] = bias[tid]; }
    if (tid < 6)  scen[tid] = newxyz[grp0*3 + tid];
    for (int e = tid; e < 36*64; e += 128) {
        int i = e >> 6, o = e & 63;
        float v = (i < 32) ? w[o*35 + 3 + i] : ((i < 35) ? w[o*35 + (i-32)] : 0.f);
        sWT[i*64 + o] = v;
    }
    __syncthreads();
    {   // gather: 2 threads per row; points via float4
        const int r = tid >> 1, h = tid & 1;
        const int pidx = sidx[r];
        const float4* prow = (const float4*)(points + ((size_t)b*NN + pidx)*32) + h*4;
        float4* dst = (float4*)(sX + r*RS1) + h*4;
        dst[0] = prow[0]; dst[1] = prow[1]; dst[2] = prow[2]; dst[3] = prow[3];
        if (h == 0) {
            const float* pc = xyz + ((size_t)b*NN + pidx)*3;
            const int cb = (r >> 5)*3;
            float4 v;
            v.x = pc[0] - scen[cb+0]; v.y = pc[1] - scen[cb+1];
            v.z = pc[2] - scen[cb+2]; v.w = 0.f;
            *(float4*)(sX + r*RS1 + 32) = v;
        }
    }
    __syncthreads();
    const int tx = tid & 15, ty = tid >> 4;    // ch = 4*tx+c, rows = ty+8j
    float acc[4][8];
    {
        float b0 = sb[4*tx+0], b1 = sb[4*tx+1], b2 = sb[4*tx+2], b3 = sb[4*tx+3];
#pragma unroll
        for (int j = 0; j < 8; j++) { acc[0][j]=b0; acc[1][j]=b1; acc[2][j]=b2; acc[3][j]=b3; }
    }
#pragma unroll
    for (int i4 = 0; i4 < 9; i4++) {
        float4 w4[4];
#pragma unroll
        for (int ii = 0; ii < 4; ii++)
            w4[ii] = *(const float4*)(sWT + (i4*4+ii)*64 + 4*tx);
#pragma unroll
        for (int j = 0; j < 8; j++) {
            const float4 x4 = *(const float4*)(sX + (ty+8*j)*RS1 + i4*4);
            FMA4(w4[0], x4.x, j); FMA4(w4[1], x4.y, j);
            FMA4(w4[2], x4.z, j); FMA4(w4[3], x4.w, j);
        }
    }
    float ls[4] = {0,0,0,0}, lq[4] = {0,0,0,0};
#pragma unroll
    for (int j = 0; j < 8; j++) {
        float4 v;
        v.x = acc[0][j]; v.y = acc[1][j]; v.z = acc[2][j]; v.w = acc[3][j];
        *(float4*)(g_y1 + (size_t)(row0 + ty + 8*j)*64 + 4*tx) = v;
#pragma unroll
        for (int c = 0; c < 4; c++) { float y = acc[c][j]; ls[c] += y; lq[c] += y*y; }
    }
    *(float4*)&sred[ty][4*tx] = make_float4(ls[0], ls[1], ls[2], ls[3]);
    __syncthreads();
    if (tid < 64) {
        float t = 0.f;
#pragma unroll
        for (int yy = 0; yy < 8; yy++) t += sred[yy][tid];
        atomicAdd(&g_sum1[tid], (double)t);
    }
    __syncthreads();
    *(float4*)&sred[ty][4*tx] = make_float4(lq[0], lq[1], lq[2], lq[3]);
    __syncthreads();
    if (tid < 64) {
        float t = 0.f;
#pragma unroll
        for (int yy = 0; yy < 8; yy++) t += sred[yy][tid];
        atomicAdd(&g_sq1[tid], (double)t);
    }
}

// ---------------- layer 2: BN1+ReLU(64) -> 64 -------------------------------
__global__ __launch_bounds__(128) void k_layer2(const float* __restrict__ w,
                                                const float* __restrict__ bias) {
    __shared__ __align__(16) float sX[64*RS2];
    __shared__ __align__(16) float sWT[64*64];
    __shared__ __align__(16) float sred[8][64];
    __shared__ __align__(16) float sa[64], sc[64];
    __shared__ float sb[64];
    const int tid = threadIdx.x;
    const int row0 = blockIdx.x * 64;
    if (tid < 64) { sa[tid] = g_a1[tid]; sc[tid] = g_c1[tid]; sb[tid] = bias[tid]; }
    for (int e = tid; e < 64*64; e += 128) {
        int i = e >> 6, o = e & 63;
        sWT[i*64 + o] = w[o*64 + i];
    }
    __syncthreads();
    for (int e = tid; e < 64*16; e += 128) {
        int r = e >> 4, q = e & 15;
        float4 v = *(const float4*)(g_y1 + (size_t)(row0 + r)*64 + q*4);
        float4 A = *(const float4*)(sa + q*4);
        float4 C = *(const float4*)(sc + q*4);
        v.x = fmaxf(fmaf(A.x, v.x, C.x), 0.f);
        v.y = fmaxf(fmaf(A.y, v.y, C.y), 0.f);
        v.z = fmaxf(fmaf(A.z, v.z, C.z), 0.f);
        v.w = fmaxf(fmaf(A.w, v.w, C.w), 0.f);
        *(float4*)(sX + r*RS2 + q*4) = v;
    }
    __syncthreads();
    const int tx = tid & 15, ty = tid >> 4;
    float acc[4][8];
    {
        float b0 = sb[4*tx+0], b1 = sb[4*tx+1], b2 = sb[4*tx+2], b3 = sb[4*tx+3];
#pragma unroll
        for (int j = 0; j < 8; j++) { acc[0][j]=b0; acc[1][j]=b1; acc[2][j]=b2; acc[3][j]=b3; }
    }
#pragma unroll
    for (int i4 = 0; i4 < 16; i4++) {
        float4 w4[4];
#pragma unroll
        for (int ii = 0; ii < 4; ii++)
            w4[ii] = *(const float4*)(sWT + (i4*4+ii)*64 + 4*tx);
#pragma unroll
        for (int j = 0; j < 8; j++) {
            const float4 x4 = *(const float4*)(sX + (ty+8*j)*RS2 + i4*4);
            FMA4(w4[0], x4.x, j); FMA4(w4[1], x4.y, j);
            FMA4(w4[2], x4.z, j); FMA4(w4[3], x4.w, j);
        }
    }
    float ls[4] = {0,0,0,0}, lq[4] = {0,0,0,0};
#pragma unroll
    for (int j = 0; j < 8; j++) {
        float4 v;
        v.x = acc[0][j]; v.y = acc[1][j]; v.z = acc[2][j]; v.w = acc[3][j];
        *(float4*)(g_y2 + (size_t)(row0 + ty + 8*j)*64 + 4*tx) = v;
#pragma unroll
        for (int c = 0; c < 4; c++) { float y = acc[c][j]; ls[c] += y; lq[c] += y*y; }
    }
    *(float4*)&sred[ty][4*tx] = make_float4(ls[0], ls[1], ls[2], ls[3]);
    __syncthreads();
    if (tid < 64) {
        float t = 0.f;
#pragma unroll
        for (int yy = 0; yy < 8; yy++) t += sred[yy][tid];
        atomicAdd(&g_sum2[tid], (double)t);
    }
    __syncthreads();
    *(float4*)&sred[ty][4*tx] = make_float4(lq[0], lq[1], lq[2], lq[3]);
    __syncthreads();
    if (tid < 64) {
        float t = 0.f;
#pragma unroll
        for (int yy = 0; yy < 8; yy++) t += sred[yy][tid];
        atomicAdd(&g_sq2[tid], (double)t);
    }
}

// ---------------- layer 3: BN2+ReLU(64) -> 128, stats + max/min over k ------
__global__ __launch_bounds__(128) void k_layer3(const float* __restrict__ w,
                                                const float* __restrict__ bias) {
    __shared__ __align__(16) float sX[32*RS2];
    __shared__ __align__(16) float sWT[64*128];
    __shared__ __align__(16) float sred[4][128];
    __shared__ __align__(16) float sa[64], sc[64];
    __shared__ float sb[128];
    const int tid = threadIdx.x;
    const int grp = blockIdx.x;
    const int row0 = grp * 32;
    if (tid < 64)  { sa[tid] = g_a2[tid]; sc[tid] = g_c2[tid]; }
    if (tid < 128) sb[tid] = bias[tid];
    for (int e = tid; e < 64*128; e += 128) {
        int i = e >> 7, o = e & 127;
        sWT[i*128 + o] = w[o*64 + i];
    }
    __syncthreads();
    for (int e = tid; e < 32*16; e += 128) {
        int r = e >> 4, q = e & 15;
        float4 v = *(const float4*)(g_y2 + (size_t)(row0 + r)*64 + q*4);
        float4 A = *(const float4*)(sa + q*4);
        float4 C = *(const float4*)(sc + q*4);
        v.x = fmaxf(fmaf(A.x, v.x, C.x), 0.f);
        v.y = fmaxf(fmaf(A.y, v.y, C.y), 0.f);
        v.z = fmaxf(fmaf(A.z, v.z, C.z), 0.f);
        v.w = fmaxf(fmaf(A.w, v.w, C.w), 0.f);
        *(float4*)(sX + r*RS2 + q*4) = v;
    }
    __syncthreads();
    const int tx = tid & 31, ty = tid >> 5;    // ch = 4*tx+c (128), rows = ty+4j (32)
    float acc[4][8];
    {
        float b0 = sb[4*tx+0], b1 = sb[4*tx+1], b2 = sb[4*tx+2], b3 = sb[4*tx+3];
#pragma unroll
        for (int j = 0; j < 8; j++) { acc[0][j]=b0; acc[1][j]=b1; acc[2][j]=b2; acc[3][j]=b3; }
    }
#pragma unroll
    for (int i4 = 0; i4 < 16; i4++) {
        float4 w4[4];
#pragma unroll
        for (int ii = 0; ii < 4; ii++)
            w4[ii] = *(const float4*)(sWT + (i4*4+ii)*128 + 4*tx);
#pragma unroll
        for (int j = 0; j < 8; j++) {
            const float4 x4 = *(const float4*)(sX + (ty+4*j)*RS2 + i4*4);
            FMA4(w4[0], x4.x, j); FMA4(w4[1], x4.y, j);
            FMA4(w4[2], x4.z, j); FMA4(w4[3], x4.w, j);
        }
    }
    float ls[4] = {0,0,0,0}, lq[4] = {0,0,0,0};
    float lx[4] = {-1e30f,-1e30f,-1e30f,-1e30f};
    float ln[4] = { 1e30f, 1e30f, 1e30f, 1e30f};
#pragma unroll
    for (int c = 0; c < 4; c++)
#pragma unroll
        for (int j = 0; j < 8; j++) {
            float y = acc[c][j];
            ls[c] += y; lq[c] += y*y;
            lx[c] = fmaxf(lx[c], y); ln[c] = fminf(ln[c], y);
        }
    *(float4*)&sred[ty][4*tx] = make_float4(ls[0], ls[1], ls[2], ls[3]);
    __syncthreads();
    if (tid < 128) {
        float t = sred[0][tid] + sred[1][tid] + sred[2][tid] + sred[3][tid];
        atomicAdd(&g_sum3[tid], (double)t);
    }
    __syncthreads();
    *(float4*)&sred[ty][4*tx] = make_float4(lq[0], lq[1], lq[2], lq[3]);
    __syncthreads();
    if (tid < 128) {
        float t = sred[0][tid] + sred[1][tid] + sred[2][tid] + sred[3][tid];
        atomicAdd(&g_sq3[tid], (double)t);
    }
    __syncthreads();
    *(float4*)&sred[ty][4*tx] = make_float4(lx[0], lx[1], lx[2], lx[3]);
    __syncthreads();
    if (tid < 128) {
        float t = fmaxf(fmaxf(sred[0][tid], sred[1][tid]),
                        fmaxf(sred[2][tid], sred[3][tid]));
        g_mx[(size_t)grp*128 + tid] = t;
    }
    __syncthreads();
    *(float4*)&sred[ty][4*tx] = make_float4(ln[0], ln[1], ln[2], ln[3]);
    __syncthreads();
    if (tid < 128) {
        float t = fminf(fminf(sred[0][tid], sred[1][tid]),
                        fminf(sred[2][tid], sred[3][tid]));
        g_mn[(size_t)grp*128 + tid] = t;
    }
}

// ---------------- BN parameter derivation -----------------------------------
__global__ void k_bn(int layer, const float* __restrict__ gg,
                     const float* __restrict__ be, int n) {
    int i = threadIdx.x;
    if (i >= n) return;
    const double* sum; const double* sq; float* a; float* c;
    if (layer == 0)      { sum = g_sum1; sq = g_sq1; a = g_a1; c = g_c1; }
    else if (layer == 1) { sum = g_sum2; sq = g_sq2; a = g_a2; c = g_c2; }
    else                 { sum = g_sum3; sq = g_sq3; a = g_a3; c = g_c3; }
    const double invM = 1.0 / (double)M_ROWS;
    double mean = sum[i] * invM;
    double var  = sq[i] * invM - mean * mean;
    double A = (double)gg[i] / sqrt(var + 1e-5);
    a[i] = (float)A;
    c[i] = (float)((double)be[i] - A * mean);
}

// ---------------- final -----------------------------------------------------
__global__ __launch_bounds__(256) void k_final(float* __restrict__ out) {
    int gid = blockIdx.x * 256 + threadIdx.x;
    int s  = gid & 1023;
    int ch = (gid >> 10) & 127;
    int b  = gid >> 17;
    float A = g_a3[ch], C = g_c3[ch];
    size_t gi = ((size_t)((b << 10) | s))*128 + ch;
    float m = (A >= 0.f) ? g_mx[gi] : g_mn[gi];
    out[OUT_XYZ_ELEMS + gid] = fmaxf(fmaf(A, m, C), 0.f);
}

// ---------------- launch ----------------------------------------------------
extern "C" void kernel_launch(void* const* d_in, const int* in_sizes, int n_in,
                              void* d_out, int out_size) {
    const float* xyz    = (const float*)d_in[0];
    const float* points = (const float*)d_in[1];
    const float* w0  = (const float*)d_in[2];
    const float* b0  = (const float*)d_in[3];
    const float* g0  = (const float*)d_in[4];
    const float* be0 = (const float*)d_in[5];
    const float* w1  = (const float*)d_in[6];
    const float* b1  = (const float*)d_in[7];
    const float* g1  = (const float*)d_in[8];
    const float* be1 = (const float*)d_in[9];
    const float* w2  = (const float*)d_in[10];
    const float* b2  = (const float*)d_in[11];
    const float* g2  = (const float*)d_in[12];
    const float* be2 = (const float*)d_in[13];
    float* out = (float*)d_out;
    (void)in_sizes; (void)n_in; (void)out_size;

    const size_t smem_xyz = (size_t)3 * NN * sizeof(float);   // 48KB dynamic

    k_init<<<1, 128>>>();
    k_fps<<<BB, 512>>>(xyz, out);
    k_ball<<<dim3(128, BB), 256, smem_xyz>>>(xyz, out);
    k_layer1<<<M_ROWS/64, 128>>>(xyz, points, out, w0, b0);
    k_bn<<<1, 128>>>(0, g0, be0, 64);
    k_layer2<<<M_ROWS/64, 128>>>(w1, b1);
    k_bn<<<1, 128>>>(1, g1, be1, 64);
    k_layer3<<<M_ROWS/32, 128>>>(w2, b2);
    k_bn<<<1, 128>>>(2, g2, be2, 128);
    k_final<<<(BB*128*SS)/256, 256>>>(out);
}

// round 4
// speedup vs baseline: 2.0227x; 1.8295x over previous
#include <cuda_runtime.h>
#include <math.h>

#define BB 16
#define NN 4096
#define SS 1024
#define KK 32
#define M_ROWS (BB*SS*KK)        // 524288
#define OUT_XYZ_ELEMS (BB*SS*3)

#define RS1 40
#define RS2 68
#define TILES12 8     // 1024 blocks * 8 tiles = 8192 tiles of 64 rows
#define TILES3  16    // 1024 blocks * 16 tiles = 16384 groups of 32 rows

// packed f32x2 helpers (sm_103a)
#define ADD2(o,a,b) asm("add.rn.f32x2 %0,%1,%2;" : "=l"(o) : "l"(a), "l"(b))
#define MUL2(o,a,b) asm("mul.rn.f32x2 %0,%1,%2;" : "=l"(o) : "l"(a), "l"(b))
#define PACK2(o,lo,hi) asm("mov.b64 %0,{%1,%2};" : "=l"(o) : "f"(lo), "f"(hi))
#define UNPACK2(lo,hi,v) asm("mov.b64 {%0,%1},%2;" : "=f"(lo), "=f"(hi) : "l"(v))
#define REDUX_MAX(o,v) asm("redux.sync.max.s32 %0,%1,0xffffffff;" : "=r"(o) : "r"(v))
#define REDUX_MIN(o,v) asm("redux.sync.min.s32 %0,%1,0xffffffff;" : "=r"(o) : "r"(v))

// ---------------- scratch ----------------------------------------------------
__device__ float  g_y1[M_ROWS*64];
__device__ float  g_y2[M_ROWS*64];
__device__ float  g_mx[BB*SS*128];
__device__ float  g_mn[BB*SS*128];
__device__ int    g_ball[M_ROWS];
__device__ double g_sum1[64],  g_sq1[64];
__device__ double g_sum2[64],  g_sq2[64];
__device__ double g_sum3[128], g_sq3[128];
__device__ float  g_a1[64], g_c1[64];
__device__ float  g_a2[64], g_c2[64];
__device__ float  g_a3[128], g_c3[128];

__global__ void k_init() {
    int t = threadIdx.x;
    if (t < 64)  { g_sum1[t]=0.0; g_sq1[t]=0.0; g_sum2[t]=0.0; g_sq2[t]=0.0; }
    if (t < 128) { g_sum3[t]=0.0; g_sq3[t]=0.0; }
}

// ---------------- FPS: packed f32x2 distances, redux-based argmax ------------
// Exact semantics: dist = min(dist, sum((p-c)^2)) with mul/add rounding
// identical to the reference (x + (-c) == x - c exactly; no FMA contraction
// because mul.rn and add.rn are separate instructions). Argmax with global
// first-index tie-break via redux(max on dist bits) + redux(min on index).
__global__ __launch_bounds__(512) void k_fps(const float* __restrict__ xyz,
                                             float* __restrict__ newxyz) {
    extern __shared__ float sm[];                  // 3*NN floats (48KB)
    float* sxs = sm; float* sys = sm + NN; float* szs = sm + 2*NN;
    __shared__ float swv[16];
    __shared__ int   swi[16];
    __shared__ float scen[3];
    const int b = blockIdx.x, tid = threadIdx.x;
    const float* base = xyz + (size_t)b*NN*3;
    float pxs[8], pys[8], pzs[8], dist[8];
#pragma unroll
    for (int k = 0; k < 8; k++) {
        const int i = tid + (k << 9);
        float x = base[3*i+0], y = base[3*i+1], z = base[3*i+2];
        pxs[k]=x; pys[k]=y; pzs[k]=z;
        sxs[i]=x; sys[i]=y; szs[i]=z;
        dist[k] = 1e10f;
    }
    unsigned long long px2[4], py2[4], pz2[4];
#pragma unroll
    for (int j = 0; j < 4; j++) {
        PACK2(px2[j], pxs[2*j], pxs[2*j+1]);
        PACK2(py2[j], pys[2*j], pys[2*j+1]);
        PACK2(pz2[j], pzs[2*j], pzs[2*j+1]);
    }
    float* outc = newxyz + (size_t)b*SS*3;
    if (tid == 0) {
        scen[0]=sxs[0]; scen[1]=sys[0]; scen[2]=szs[0];
        outc[0]=sxs[0]; outc[1]=sys[0]; outc[2]=szs[0];
    }
    __syncthreads();
    const int lane = tid & 31, w = tid >> 5;
    for (int it = 0; it < SS-1; it++) {
        const float ncx = -scen[0], ncy = -scen[1], ncz = -scen[2];
        unsigned long long ncx2, ncy2, ncz2;
        PACK2(ncx2, ncx, ncx); PACK2(ncy2, ncy, ncy); PACK2(ncz2, ncz, ncz);
        float bv = -1.0f;
#pragma unroll
        for (int j = 0; j < 4; j++) {
            unsigned long long dx,dy,dz,qx,qy,qz,s2,d2;
            ADD2(dx, px2[j], ncx2);
            ADD2(dy, py2[j], ncy2);
            ADD2(dz, pz2[j], ncz2);
            MUL2(qx, dx, dx); MUL2(qy, dy, dy); MUL2(qz, dz, dz);
            ADD2(s2, qx, qy); ADD2(d2, s2, qz);
            float d0, d1; UNPACK2(d0, d1, d2);
            dist[2*j]   = fminf(dist[2*j],   d0);
            dist[2*j+1] = fminf(dist[2*j+1], d1);
            bv = fmaxf(bv, dist[2*j]); bv = fmaxf(bv, dist[2*j+1]);
        }
        int bi = 0x7fffffff;
#pragma unroll
        for (int k = 7; k >= 0; k--)
            if (dist[k] == bv) bi = tid + (k << 9);
        int vmax; REDUX_MAX(vmax, __float_as_int(bv));
        int ti = (__float_as_int(bv) == vmax) ? bi : 0x7fffffff;
        int imin; REDUX_MIN(imin, ti);
        if (lane == 0) { swv[w] = __int_as_float(vmax); swi[w] = imin; }
        __syncthreads();
        if (tid < 32) {
            float v = (tid < 16) ? swv[tid] : -1.0f;
            int   i2 = (tid < 16) ? swi[tid] : 0x7fffffff;
            int vm2; REDUX_MAX(vm2, __float_as_int(v));
            int t2 = (__float_as_int(v) == vm2) ? i2 : 0x7fffffff;
            int im2; REDUX_MIN(im2, t2);
            if (tid == 0) {
                float fx = sxs[im2], fy = sys[im2], fz = szs[im2];
                scen[0]=fx; scen[1]=fy; scen[2]=fz;
                outc[3*(it+1)+0]=fx; outc[3*(it+1)+1]=fy; outc[3*(it+1)+2]=fz;
            }
        }
        __syncthreads();
    }
}

// ---------------- ball query -------------------------------------------------
__global__ __launch_bounds__(256) void k_ball(const float* __restrict__ xyz,
                                              const float* __restrict__ newxyz) {
    extern __shared__ float sm[];
    float* sx = sm; float* sy = sm + NN; float* sz = sm + 2*NN;
    const int b = blockIdx.y;
    const float* base = xyz + (size_t)b*NN*3;
    for (int i = threadIdx.x; i < NN; i += 256) {
        sx[i] = base[3*i+0]; sy[i] = base[3*i+1]; sz[i] = base[3*i+2];
    }
    __syncthreads();
    const int wid = threadIdx.x >> 5, lane = threadIdx.x & 31;
    const int s = blockIdx.x * 8 + wid;
    const int g = b * SS + s;
    const float cx = newxyz[3*g+0], cy = newxyz[3*g+1], cz = newxyz[3*g+2];
    int* out = g_ball + (size_t)g*KK;
    int count = 0, first = -1;
    for (int j0 = 0; j0 < NN && count < KK; j0 += 32) {
        const int j = j0 + lane;
        float dx = sx[j]-cx, dy = sy[j]-cy, dz = sz[j]-cz;
        float d = __fadd_rn(__fadd_rn(__fmul_rn(dx,dx), __fmul_rn(dy,dy)),
                            __fmul_rn(dz,dz));
        const bool in = !(d > 0.04f);
        unsigned m = __ballot_sync(0xffffffffu, in);
        if (first < 0 && m) first = j0 + __ffs(m) - 1;
        int pre = __popc(m & ((1u << lane) - 1u));
        if (in) { int p = count + pre; if (p < KK) out[p] = j; }
        count += __popc(m);
    }
    if (count < KK) {
        for (int t = count + lane; t < KK; t += 32) out[t] = first;
    }
}

#define FMA4(W4, xs, j) \
    acc[0][j] = fmaf((W4).x, (xs), acc[0][j]); \
    acc[1][j] = fmaf((W4).y, (xs), acc[1][j]); \
    acc[2][j] = fmaf((W4).z, (xs), acc[2][j]); \
    acc[3][j] = fmaf((W4).w, (xs), acc[3][j]);

// ---------------- layer 1 (persistent tiles) ---------------------------------
__global__ __launch_bounds__(128) void k_layer1(const float* __restrict__ xyz,
                                                const float* __restrict__ points,
                                                const float* __restrict__ newxyz,
                                                const float* __restrict__ w,
                                                const float* __restrict__ bias) {
    __shared__ __align__(16) float sX[64*RS1];
    __shared__ __align__(16) float sWT[36*64];
    __shared__ __align__(16) float sred[8][64];
    __shared__ float sb[64];
    const int tid = threadIdx.x;
    if (tid < 64) sb[tid] = bias[tid];
    for (int e = tid; e < 36*64; e += 128) {
        int i = e >> 6, o = e & 63;
        float v = (i < 32) ? w[o*35 + 3 + i] : ((i < 35) ? w[o*35 + (i-32)] : 0.f);
        sWT[i*64 + o] = v;
    }
    __syncthreads();
    const int tx = tid & 15, ty = tid >> 4;
    const float bb0 = sb[4*tx+0], bb1 = sb[4*tx+1], bb2 = sb[4*tx+2], bb3 = sb[4*tx+3];
    float ls[4] = {0,0,0,0}, lq[4] = {0,0,0,0};
    for (int t = 0; t < TILES12; t++) {
        const int row0 = (blockIdx.x*TILES12 + t) * 64;
        const int b = row0 >> 15;
        const int grp0 = row0 >> 5;
        __syncthreads();
        {
            const int r = tid >> 1, h = tid & 1;
            const int pidx = g_ball[row0 + r];
            const float4* prow = (const float4*)(points + ((size_t)b*NN + pidx)*32) + h*4;
            float4* dst = (float4*)(sX + r*RS1) + h*4;
            dst[0] = prow[0]; dst[1] = prow[1]; dst[2] = prow[2]; dst[3] = prow[3];
            if (h == 0) {
                const float* pc  = xyz + ((size_t)b*NN + pidx)*3;
                const float* cen = newxyz + (size_t)(grp0 + (r >> 5))*3;
                float4 v;
                v.x = pc[0]-cen[0]; v.y = pc[1]-cen[1]; v.z = pc[2]-cen[2]; v.w = 0.f;
                *(float4*)(sX + r*RS1 + 32) = v;
            }
        }
        __syncthreads();
        float acc[4][8];
#pragma unroll
        for (int j = 0; j < 8; j++) { acc[0][j]=bb0; acc[1][j]=bb1; acc[2][j]=bb2; acc[3][j]=bb3; }
#pragma unroll
        for (int i4 = 0; i4 < 9; i4++) {
            float4 w4[4];
#pragma unroll
            for (int ii = 0; ii < 4; ii++)
                w4[ii] = *(const float4*)(sWT + (i4*4+ii)*64 + 4*tx);
#pragma unroll
            for (int j = 0; j < 8; j++) {
                const float4 x4 = *(const float4*)(sX + (ty+8*j)*RS1 + i4*4);
                FMA4(w4[0], x4.x, j); FMA4(w4[1], x4.y, j);
                FMA4(w4[2], x4.z, j); FMA4(w4[3], x4.w, j);
            }
        }
#pragma unroll
        for (int j = 0; j < 8; j++) {
            float4 v;
            v.x = acc[0][j]; v.y = acc[1][j]; v.z = acc[2][j]; v.w = acc[3][j];
            *(float4*)(g_y1 + (size_t)(row0 + ty + 8*j)*64 + 4*tx) = v;
#pragma unroll
            for (int c = 0; c < 4; c++) { float y = acc[c][j]; ls[c] += y; lq[c] += y*y; }
        }
    }
    __syncthreads();
    *(float4*)&sred[ty][4*tx] = make_float4(ls[0], ls[1], ls[2], ls[3]);
    __syncthreads();
    if (tid < 64) {
        float t = 0.f;
#pragma unroll
        for (int yy = 0; yy < 8; yy++) t += sred[yy][tid];
        atomicAdd(&g_sum1[tid], (double)t);
    }
    __syncthreads();
    *(float4*)&sred[ty][4*tx] = make_float4(lq[0], lq[1], lq[2], lq[3]);
    __syncthreads();
    if (tid < 64) {
        float t = 0.f;
#pragma unroll
        for (int yy = 0; yy < 8; yy++) t += sred[yy][tid];
        atomicAdd(&g_sq1[tid], (double)t);
    }
}

// ---------------- layer 2 (persistent tiles) ---------------------------------
__global__ __launch_bounds__(128) void k_layer2(const float* __restrict__ w,
                                                const float* __restrict__ bias) {
    __shared__ __align__(16) float sX[64*RS2];
    __shared__ __align__(16) float sWT[64*64];
    __shared__ __align__(16) float sred[8][64];
    __shared__ __align__(16) float sa[64], sc[64];
    __shared__ float sb[64];
    const int tid = threadIdx.x;
    if (tid < 64) { sa[tid] = g_a1[tid]; sc[tid] = g_c1[tid]; sb[tid] = bias[tid]; }
    for (int e = tid; e < 64*64; e += 128) {
        int i = e >> 6, o = e & 63;
        sWT[i*64 + o] = w[o*64 + i];
    }
    __syncthreads();
    const int tx = tid & 15, ty = tid >> 4;
    const float bb0 = sb[4*tx+0], bb1 = sb[4*tx+1], bb2 = sb[4*tx+2], bb3 = sb[4*tx+3];
    float ls[4] = {0,0,0,0}, lq[4] = {0,0,0,0};
    for (int t = 0; t < TILES12; t++) {
        const int row0 = (blockIdx.x*TILES12 + t) * 64;
        __syncthreads();
        for (int e = tid; e < 64*16; e += 128) {
            int r = e >> 4, q = e & 15;
            float4 v = *(const float4*)(g_y1 + (size_t)(row0 + r)*64 + q*4);
            float4 A = *(const float4*)(sa + q*4);
            float4 C = *(const float4*)(sc + q*4);
            v.x = fmaxf(fmaf(A.x, v.x, C.x), 0.f);
            v.y = fmaxf(fmaf(A.y, v.y, C.y), 0.f);
            v.z = fmaxf(fmaf(A.z, v.z, C.z), 0.f);
            v.w = fmaxf(fmaf(A.w, v.w, C.w), 0.f);
            *(float4*)(sX + r*RS2 + q*4) = v;
        }
        __syncthreads();
        float acc[4][8];
#pragma unroll
        for (int j = 0; j < 8; j++) { acc[0][j]=bb0; acc[1][j]=bb1; acc[2][j]=bb2; acc[3][j]=bb3; }
#pragma unroll
        for (int i4 = 0; i4 < 16; i4++) {
            float4 w4[4];
#pragma unroll
            for (int ii = 0; ii < 4; ii++)
                w4[ii] = *(const float4*)(sWT + (i4*4+ii)*64 + 4*tx);
#pragma unroll
            for (int j = 0; j < 8; j++) {
                const float4 x4 = *(const float4*)(sX + (ty+8*j)*RS2 + i4*4);
                FMA4(w4[0], x4.x, j); FMA4(w4[1], x4.y, j);
                FMA4(w4[2], x4.z, j); FMA4(w4[3], x4.w, j);
            }
        }
#pragma unroll
        for (int j = 0; j < 8; j++) {
            float4 v;
            v.x = acc[0][j]; v.y = acc[1][j]; v.z = acc[2][j]; v.w = acc[3][j];
            *(float4*)(g_y2 + (size_t)(row0 + ty + 8*j)*64 + 4*tx) = v;
#pragma unroll
            for (int c = 0; c < 4; c++) { float y = acc[c][j]; ls[c] += y; lq[c] += y*y; }
        }
    }
    __syncthreads();
    *(float4*)&sred[ty][4*tx] = make_float4(ls[0], ls[1], ls[2], ls[3]);
    __syncthreads();
    if (tid < 64) {
        float t = 0.f;
#pragma unroll
        for (int yy = 0; yy < 8; yy++) t += sred[yy][tid];
        atomicAdd(&g_sum2[tid], (double)t);
    }
    __syncthreads();
    *(float4*)&sred[ty][4*tx] = make_float4(lq[0], lq[1], lq[2], lq[3]);
    __syncthreads();
    if (tid < 64) {
        float t = 0.f;
#pragma unroll
        for (int yy = 0; yy < 8; yy++) t += sred[yy][tid];
        atomicAdd(&g_sq2[tid], (double)t);
    }
}

// ---------------- layer 3 (persistent tiles, max/min over k) -----------------
__global__ __launch_bounds__(128) void k_layer3(const float* __restrict__ w,
                                                const float* __restrict__ bias) {
    __shared__ __align__(16) float sX[32*RS2];
    __shared__ __align__(16) float sWT[64*128];
    __shared__ __align__(16) float sredx[4][128];
    __shared__ __align__(16) float sredn[4][128];
    __shared__ __align__(16) float sa[64], sc[64];
    __shared__ float sb[128];
    const int tid = threadIdx.x;
    if (tid < 64)  { sa[tid] = g_a2[tid]; sc[tid] = g_c2[tid]; }
    if (tid < 128) sb[tid] = bias[tid];
    for (int e = tid; e < 64*128; e += 128) {
        int i = e >> 7, o = e & 127;
        sWT[i*128 + o] = w[o*64 + i];
    }
    __syncthreads();
    const int tx = tid & 31, ty = tid >> 5;
    const float bb0 = sb[4*tx+0], bb1 = sb[4*tx+1], bb2 = sb[4*tx+2], bb3 = sb[4*tx+3];
    float ls[4] = {0,0,0,0}, lq[4] = {0,0,0,0};
    for (int t = 0; t < TILES3; t++) {
        const int grp = blockIdx.x*TILES3 + t;
        const int row0 = grp * 32;
        __syncthreads();
        for (int e = tid; e < 32*16; e += 128) {
            int r = e >> 4, q = e & 15;
            float4 v = *(const float4*)(g_y2 + (size_t)(row0 + r)*64 + q*4);
            float4 A = *(const float4*)(sa + q*4);
            float4 C = *(const float4*)(sc + q*4);
            v.x = fmaxf(fmaf(A.x, v.x, C.x), 0.f);
            v.y = fmaxf(fmaf(A.y, v.y, C.y), 0.f);
            v.z = fmaxf(fmaf(A.z, v.z, C.z), 0.f);
            v.w = fmaxf(fmaf(A.w, v.w, C.w), 0.f);
            *(float4*)(sX + r*RS2 + q*4) = v;
        }
        __syncthreads();
        float acc[4][8];
#pragma unroll
        for (int j = 0; j < 8; j++) { acc[0][j]=bb0; acc[1][j]=bb1; acc[2][j]=bb2; acc[3][j]=bb3; }
#pragma unroll
        for (int i4 = 0; i4 < 16; i4++) {
            float4 w4[4];
#pragma unroll
            for (int ii = 0; ii < 4; ii++)
                w4[ii] = *(const float4*)(sWT + (i4*4+ii)*128 + 4*tx);
#pragma unroll
            for (int j = 0; j < 8; j++) {
                const float4 x4 = *(const float4*)(sX + (ty+4*j)*RS2 + i4*4);
                FMA4(w4[0], x4.x, j); FMA4(w4[1], x4.y, j);
                FMA4(w4[2], x4.z, j); FMA4(w4[3], x4.w, j);
            }
        }
        float lx[4] = {-1e30f,-1e30f,-1e30f,-1e30f};
        float ln[4] = { 1e30f, 1e30f, 1e30f, 1e30f};
#pragma unroll
        for (int c = 0; c < 4; c++)
#pragma unroll
            for (int j = 0; j < 8; j++) {
                float y = acc[c][j];
                ls[c] += y; lq[c] += y*y;
                lx[c] = fmaxf(lx[c], y); ln[c] = fminf(ln[c], y);
            }
        *(float4*)&sredx[ty][4*tx] = make_float4(lx[0], lx[1], lx[2], lx[3]);
        *(float4*)&sredn[ty][4*tx] = make_float4(ln[0], ln[1], ln[2], ln[3]);
        __syncthreads();
        {
            float mx = fmaxf(fmaxf(sredx[0][tid], sredx[1][tid]),
                             fmaxf(sredx[2][tid], sredx[3][tid]));
            float mn = fminf(fminf(sredn[0][tid], sredn[1][tid]),
                             fminf(sredn[2][tid], sredn[3][tid]));
            g_mx[(size_t)grp*128 + tid] = mx;
            g_mn[(size_t)grp*128 + tid] = mn;
        }
    }
    __syncthreads();
    *(float4*)&sredx[ty][4*tx] = make_float4(ls[0], ls[1], ls[2], ls[3]);
    *(float4*)&sredn[ty][4*tx] = make_float4(lq[0], lq[1], lq[2], lq[3]);
    __syncthreads();
    {
        float ts = sredx[0][tid] + sredx[1][tid] + sredx[2][tid] + sredx[3][tid];
        float tq = sredn[0][tid] + sredn[1][tid] + sredn[2][tid] + sredn[3][tid];
        atomicAdd(&g_sum3[tid], (double)ts);
        atomicAdd(&g_sq3[tid], (double)tq);
    }
}

// ---------------- BN parameter derivation ------------------------------------
__global__ void k_bn(int layer, const float* __restrict__ gg,
                     const float* __restrict__ be, int n) {
    int i = threadIdx.x;
    if (i >= n) return;
    const double* sum; const double* sq; float* a; float* c;
    if (layer == 0)      { sum = g_sum1; sq = g_sq1; a = g_a1; c = g_c1; }
    else if (layer == 1) { sum = g_sum2; sq = g_sq2; a = g_a2; c = g_c2; }
    else                 { sum = g_sum3; sq = g_sq3; a = g_a3; c = g_c3; }
    const double invM = 1.0 / (double)M_ROWS;
    double mean = sum[i] * invM;
    double var  = sq[i] * invM - mean * mean;
    double A = (double)gg[i] / sqrt(var + 1e-5);
    a[i] = (float)A;
    c[i] = (float)((double)be[i] - A * mean);
}

// ---------------- final ------------------------------------------------------
__global__ __launch_bounds__(256) void k_final(float* __restrict__ out) {
    int gid = blockIdx.x * 256 + threadIdx.x;
    int s  = gid & 1023;
    int ch = (gid >> 10) & 127;
    int b  = gid >> 17;
    float A = g_a3[ch], C = g_c3[ch];
    size_t gi = ((size_t)((b << 10) | s))*128 + ch;
    float m = (A >= 0.f) ? g_mx[gi] : g_mn[gi];
    out[OUT_XYZ_ELEMS + gid] = fmaxf(fmaf(A, m, C), 0.f);
}

// ---------------- launch -----------------------------------------------------
extern "C" void kernel_launch(void* const* d_in, const int* in_sizes, int n_in,
                              void* d_out, int out_size) {
    const float* xyz    = (const float*)d_in[0];
    const float* points = (const float*)d_in[1];
    const float* w0  = (const float*)d_in[2];
    const float* b0  = (const float*)d_in[3];
    const float* g0  = (const float*)d_in[4];
    const float* be0 = (const float*)d_in[5];
    const float* w1  = (const float*)d_in[6];
    const float* b1  = (const float*)d_in[7];
    const float* g1  = (const float*)d_in[8];
    const float* be1 = (const float*)d_in[9];
    const float* w2  = (const float*)d_in[10];
    const float* b2  = (const float*)d_in[11];
    const float* g2  = (const float*)d_in[12];
    const float* be2 = (const float*)d_in[13];
    float* out = (float*)d_out;
    (void)in_sizes; (void)n_in; (void)out_size;

    const size_t smem_xyz = (size_t)3 * NN * sizeof(float);   // 48KB dynamic
    static int attr_done = 0;
    if (!attr_done) {
        cudaFuncSetAttribute(k_fps, cudaFuncAttributeMaxDynamicSharedMemorySize,
                             (int)smem_xyz);
        attr_done = 1;
    }

    k_init<<<1, 128>>>();
    k_fps<<<BB, 512, smem_xyz>>>(xyz, out);
    k_ball<<<dim3(128, BB), 256, smem_xyz>>>(xyz, out);
    k_layer1<<<1024, 128>>>(xyz, points, out, w0, b0);
    k_bn<<<1, 128>>>(0, g0, be0, 64);
    k_layer2<<<1024, 128>>>(w1, b1);
    k_bn<<<1, 128>>>(1, g1, be1, 64);
    k_layer3<<<1024, 128>>>(w2, b2);
    k_bn<<<1, 128>>>(2, g2, be2, 128);
    k_final<<<(BB*128*SS)/256, 256>>>(out);
}

// round 5
// speedup vs baseline: 2.1826x; 1.0791x over previous
#include <cuda_runtime.h>
#include <math.h>

#define BB 16
#define NN 4096
#define SS 1024
#define KK 32
#define M_ROWS (BB*SS*KK)        // 524288
#define OUT_XYZ_ELEMS (BB*SS*3)

#define RS1 40
#define RS2 68
#define TILES12 8     // 1024 blocks * 8 tiles of 64 rows
#define TILES3  16    // 1024 blocks * 16 groups of 32 rows

// packed f32x2 helpers (sm_103a)
#define ADD2(o,a,b) asm("add.rn.f32x2 %0,%1,%2;" : "=l"(o) : "l"(a), "l"(b))
#define MUL2(o,a,b) asm("mul.rn.f32x2 %0,%1,%2;" : "=l"(o) : "l"(a), "l"(b))
#define PACK2(o,lo,hi) asm("mov.b64 %0,{%1,%2};" : "=l"(o) : "f"(lo), "f"(hi))
#define UNPACK2(lo,hi,v) asm("mov.b64 {%0,%1},%2;" : "=f"(lo), "=f"(hi) : "l"(v))
#define REDUX_MAX(o,v) asm("redux.sync.max.s32 %0,%1,0xffffffff;" : "=r"(o) : "r"(v))
#define REDUX_MIN(o,v) asm("redux.sync.min.s32 %0,%1,0xffffffff;" : "=r"(o) : "r"(v))

// ---------------- scratch ----------------------------------------------------
__device__ float  g_y1[M_ROWS*64];
__device__ float  g_y2[M_ROWS*64];
__device__ float  g_mx[BB*SS*128];
__device__ float  g_mn[BB*SS*128];
__device__ int    g_ball[M_ROWS];
__device__ double g_sum1[64],  g_sq1[64];
__device__ double g_sum2[64],  g_sq2[64];
__device__ double g_sum3[128], g_sq3[128];
__device__ float  g_a1[64], g_c1[64];
__device__ float  g_a2[64], g_c2[64];
__device__ float  g_a3[128], g_c3[128];

__global__ void k_init() {
    int t = threadIdx.x;
    if (t < 64)  { g_sum1[t]=0.0; g_sq1[t]=0.0; g_sum2[t]=0.0; g_sq2[t]=0.0; }
    if (t < 128) { g_sum3[t]=0.0; g_sq3[t]=0.0; }
}

// ---------------- FPS: one barrier/iter, all-warp final reduce ----------------
// Exact reference semantics: dist=min(dist, sum((p-c)^2)) with uncontracted
// mul/add rounding; global argmax with first-index tie-break (redux max on
// positive-float bits, then redux min on index). Double-buffered partials
// remove the post-reduce barrier; every warp redoes the 16-way final reduce
// and loads the centroid coords straight from the smem point table.
__global__ __launch_bounds__(512) void k_fps(const float* __restrict__ xyz,
                                             float* __restrict__ newxyz) {
    extern __shared__ float sm[];                  // 3*NN floats (48KB)
    float* sxs = sm; float* sys = sm + NN; float* szs = sm + 2*NN;
    __shared__ float swv[2][16];
    __shared__ int   swi[2][16];
    const int b = blockIdx.x, tid = threadIdx.x;
    const float* base = xyz + (size_t)b*NN*3;
    float pxs[8], pys[8], pzs[8], dist[8];
#pragma unroll
    for (int k = 0; k < 8; k++) {
        const int i = tid + (k << 9);
        float x = base[3*i+0], y = base[3*i+1], z = base[3*i+2];
        pxs[k]=x; pys[k]=y; pzs[k]=z;
        sxs[i]=x; sys[i]=y; szs[i]=z;
        dist[k] = 1e10f;
    }
    unsigned long long px2[4], py2[4], pz2[4];
#pragma unroll
    for (int j = 0; j < 4; j++) {
        PACK2(px2[j], pxs[2*j], pxs[2*j+1]);
        PACK2(py2[j], pys[2*j], pys[2*j+1]);
        PACK2(pz2[j], pzs[2*j], pzs[2*j+1]);
    }
    float* outc = newxyz + (size_t)b*SS*3;
    __syncthreads();
    float ccx = sxs[0], ccy = sys[0], ccz = szs[0];
    if (tid == 0) { outc[0]=ccx; outc[1]=ccy; outc[2]=ccz; }
    const int lane = tid & 31, w = tid >> 5;
    for (int it = 0; it < SS-1; it++) {
        const int pb = it & 1;
        const float ncx = -ccx, ncy = -ccy, ncz = -ccz;
        unsigned long long ncx2, ncy2, ncz2;
        PACK2(ncx2, ncx, ncx); PACK2(ncy2, ncy, ncy); PACK2(ncz2, ncz, ncz);
        float bv = -1.0f;
#pragma unroll
        for (int j = 0; j < 4; j++) {
            unsigned long long dx,dy,dz,qx,qy,qz,s2,d2;
            ADD2(dx, px2[j], ncx2);
            ADD2(dy, py2[j], ncy2);
            ADD2(dz, pz2[j], ncz2);
            MUL2(qx, dx, dx); MUL2(qy, dy, dy); MUL2(qz, dz, dz);
            ADD2(s2, qx, qy); ADD2(d2, s2, qz);
            float d0, d1; UNPACK2(d0, d1, d2);
            dist[2*j]   = fminf(dist[2*j],   d0);
            dist[2*j+1] = fminf(dist[2*j+1], d1);
            bv = fmaxf(bv, dist[2*j]); bv = fmaxf(bv, dist[2*j+1]);
        }
        int bi = 0x7fffffff;
#pragma unroll
        for (int k = 7; k >= 0; k--)
            if (dist[k] == bv) bi = tid + (k << 9);
        int vmax; REDUX_MAX(vmax, __float_as_int(bv));
        int ti = (__float_as_int(bv) == vmax) ? bi : 0x7fffffff;
        int imin; REDUX_MIN(imin, ti);
        if (lane == 0) { swv[pb][w] = __int_as_float(vmax); swi[pb][w] = imin; }
        __syncthreads();
        float v  = (lane < 16) ? swv[pb][lane] : -1.0f;
        int   i2 = (lane < 16) ? swi[pb][lane] : 0x7fffffff;
        int vg; REDUX_MAX(vg, __float_as_int(v));
        int t2 = (__float_as_int(v) == vg) ? i2 : 0x7fffffff;
        int ig; REDUX_MIN(ig, t2);
        ccx = sxs[ig]; ccy = sys[ig]; ccz = szs[ig];
        if (tid == 0) {
            outc[3*(it+1)+0]=ccx; outc[3*(it+1)+1]=ccy; outc[3*(it+1)+2]=ccz;
        }
    }
}

// ---------------- ball query: 1024 threads, 32 centroids per block -----------
__global__ __launch_bounds__(1024) void k_ball(const float* __restrict__ xyz,
                                               const float* __restrict__ newxyz) {
    extern __shared__ float sm[];
    float* sx = sm; float* sy = sm + NN; float* sz = sm + 2*NN;
    const int b = blockIdx.y;
    const float* base = xyz + (size_t)b*NN*3;
    for (int i = threadIdx.x; i < NN; i += 1024) {
        sx[i] = base[3*i+0]; sy[i] = base[3*i+1]; sz[i] = base[3*i+2];
    }
    __syncthreads();
    const int wid = threadIdx.x >> 5, lane = threadIdx.x & 31;
    const int s = blockIdx.x * 32 + wid;
    const int g = b * SS + s;
    const float cx = newxyz[3*g+0], cy = newxyz[3*g+1], cz = newxyz[3*g+2];
    int* out = g_ball + (size_t)g*KK;
    int count = 0, first = -1;
    for (int j0 = 0; j0 < NN && count < KK; j0 += 32) {
        const int j = j0 + lane;
        float dx = sx[j]-cx, dy = sy[j]-cy, dz = sz[j]-cz;
        float d = __fadd_rn(__fadd_rn(__fmul_rn(dx,dx), __fmul_rn(dy,dy)),
                            __fmul_rn(dz,dz));
        const bool in = !(d > 0.04f);
        unsigned m = __ballot_sync(0xffffffffu, in);
        if (first < 0 && m) first = j0 + __ffs(m) - 1;
        int pre = __popc(m & ((1u << lane) - 1u));
        if (in) { int p = count + pre; if (p < KK) out[p] = j; }
        count += __popc(m);
    }
    if (count < KK) {
        for (int t = count + lane; t < KK; t += 32) out[t] = first;
    }
}

#define FMA4(W4, xs, j) \
    acc[0][j] = fmaf((W4).x, (xs), acc[0][j]); \
    acc[1][j] = fmaf((W4).y, (xs), acc[1][j]); \
    acc[2][j] = fmaf((W4).z, (xs), acc[2][j]); \
    acc[3][j] = fmaf((W4).w, (xs), acc[3][j]);

// ---------------- layer 1: 256 threads, acc[4][4] ----------------------------
__global__ __launch_bounds__(256, 4) void k_layer1(const float* __restrict__ xyz,
                                                   const float* __restrict__ points,
                                                   const float* __restrict__ newxyz,
                                                   const float* __restrict__ w,
                                                   const float* __restrict__ bias) {
    __shared__ __align__(16) float sX[64*RS1];
    __shared__ __align__(16) float sWT[36*64];
    __shared__ __align__(16) float sred[16][64];
    __shared__ float sb[64];
    const int tid = threadIdx.x;
    if (tid < 64) sb[tid] = bias[tid];
    for (int e = tid; e < 36*64; e += 256) {
        int i = e >> 6, o = e & 63;
        float v = (i < 32) ? w[o*35 + 3 + i] : ((i < 35) ? w[o*35 + (i-32)] : 0.f);
        sWT[i*64 + o] = v;
    }
    __syncthreads();
    const int tx = tid & 15, ty = tid >> 4;      // ch 4*tx+c, rows ty+16j (j<4)
    const float bb0 = sb[4*tx+0], bb1 = sb[4*tx+1], bb2 = sb[4*tx+2], bb3 = sb[4*tx+3];
    float ls[4] = {0,0,0,0}, lq[4] = {0,0,0,0};
    for (int t = 0; t < TILES12; t++) {
        const int row0 = (blockIdx.x*TILES12 + t) * 64;
        const int b = row0 >> 15;
        const int grp0 = row0 >> 5;
        __syncthreads();
        {   // gather: 4 threads per row
            const int r = tid >> 2, h = tid & 3;
            const int pidx = g_ball[row0 + r];
            const float4* prow = (const float4*)(points + ((size_t)b*NN + pidx)*32) + h*2;
            float4* dst = (float4*)(sX + r*RS1) + h*2;
            dst[0] = prow[0]; dst[1] = prow[1];
            if (h == 0) {
                const float* pc  = xyz + ((size_t)b*NN + pidx)*3;
                const float* cen = newxyz + (size_t)(grp0 + (r >> 5))*3;
                float4 v;
                v.x = pc[0]-cen[0]; v.y = pc[1]-cen[1]; v.z = pc[2]-cen[2]; v.w = 0.f;
                *(float4*)(sX + r*RS1 + 32) = v;
            }
        }
        __syncthreads();
        float acc[4][4];
#pragma unroll
        for (int j = 0; j < 4; j++) { acc[0][j]=bb0; acc[1][j]=bb1; acc[2][j]=bb2; acc[3][j]=bb3; }
#pragma unroll
        for (int i4 = 0; i4 < 9; i4++) {
            float4 w4[4];
#pragma unroll
            for (int ii = 0; ii < 4; ii++)
                w4[ii] = *(const float4*)(sWT + (i4*4+ii)*64 + 4*tx);
#pragma unroll
            for (int j = 0; j < 4; j++) {
                const float4 x4 = *(const float4*)(sX + (ty+16*j)*RS1 + i4*4);
                FMA4(w4[0], x4.x, j); FMA4(w4[1], x4.y, j);
                FMA4(w4[2], x4.z, j); FMA4(w4[3], x4.w, j);
            }
        }
#pragma unroll
        for (int j = 0; j < 4; j++) {
            float4 v;
            v.x = acc[0][j]; v.y = acc[1][j]; v.z = acc[2][j]; v.w = acc[3][j];
            *(float4*)(g_y1 + (size_t)(row0 + ty + 16*j)*64 + 4*tx) = v;
#pragma unroll
            for (int c = 0; c < 4; c++) { float y = acc[c][j]; ls[c] += y; lq[c] += y*y; }
        }
    }
    __syncthreads();
    *(float4*)&sred[ty][4*tx] = make_float4(ls[0], ls[1], ls[2], ls[3]);
    __syncthreads();
    if (tid < 64) {
        float t = 0.f;
#pragma unroll
        for (int yy = 0; yy < 16; yy++) t += sred[yy][tid];
        atomicAdd(&g_sum1[tid], (double)t);
    }
    __syncthreads();
    *(float4*)&sred[ty][4*tx] = make_float4(lq[0], lq[1], lq[2], lq[3]);
    __syncthreads();
    if (tid < 64) {
        float t = 0.f;
#pragma unroll
        for (int yy = 0; yy < 16; yy++) t += sred[yy][tid];
        atomicAdd(&g_sq1[tid], (double)t);
    }
}

// ---------------- layer 2: 256 threads, acc[4][4] ----------------------------
__global__ __launch_bounds__(256, 4) void k_layer2(const float* __restrict__ w,
                                                   const float* __restrict__ bias) {
    __shared__ __align__(16) float sX[64*RS2];
    __shared__ __align__(16) float sWT[64*64];
    __shared__ __align__(16) float sred[16][64];
    __shared__ __align__(16) float sa[64], sc[64];
    __shared__ float sb[64];
    const int tid = threadIdx.x;
    if (tid < 64) { sa[tid] = g_a1[tid]; sc[tid] = g_c1[tid]; sb[tid] = bias[tid]; }
    for (int e = tid; e < 64*64; e += 256) {
        int i = e >> 6, o = e & 63;
        sWT[i*64 + o] = w[o*64 + i];
    }
    __syncthreads();
    const int tx = tid & 15, ty = tid >> 4;
    const float bb0 = sb[4*tx+0], bb1 = sb[4*tx+1], bb2 = sb[4*tx+2], bb3 = sb[4*tx+3];
    float ls[4] = {0,0,0,0}, lq[4] = {0,0,0,0};
    for (int t = 0; t < TILES12; t++) {
        const int row0 = (blockIdx.x*TILES12 + t) * 64;
        __syncthreads();
        for (int e = tid; e < 64*16; e += 256) {
            int r = e >> 4, q = e & 15;
            float4 v = *(const float4*)(g_y1 + (size_t)(row0 + r)*64 + q*4);
            float4 A = *(const float4*)(sa + q*4);
            float4 C = *(const float4*)(sc + q*4);
            v.x = fmaxf(fmaf(A.x, v.x, C.x), 0.f);
            v.y = fmaxf(fmaf(A.y, v.y, C.y), 0.f);
            v.z = fmaxf(fmaf(A.z, v.z, C.z), 0.f);
            v.w = fmaxf(fmaf(A.w, v.w, C.w), 0.f);
            *(float4*)(sX + r*RS2 + q*4) = v;
        }
        __syncthreads();
        float acc[4][4];
#pragma unroll
        for (int j = 0; j < 4; j++) { acc[0][j]=bb0; acc[1][j]=bb1; acc[2][j]=bb2; acc[3][j]=bb3; }
#pragma unroll
        for (int i4 = 0; i4 < 16; i4++) {
            float4 w4[4];
#pragma unroll
            for (int ii = 0; ii < 4; ii++)
                w4[ii] = *(const float4*)(sWT + (i4*4+ii)*64 + 4*tx);
#pragma unroll
            for (int j = 0; j < 4; j++) {
                const float4 x4 = *(const float4*)(sX + (ty+16*j)*RS2 + i4*4);
                FMA4(w4[0], x4.x, j); FMA4(w4[1], x4.y, j);
                FMA4(w4[2], x4.z, j); FMA4(w4[3], x4.w, j);
            }
        }
#pragma unroll
        for (int j = 0; j < 4; j++) {
            float4 v;
            v.x = acc[0][j]; v.y = acc[1][j]; v.z = acc[2][j]; v.w = acc[3][j];
            *(float4*)(g_y2 + (size_t)(row0 + ty + 16*j)*64 + 4*tx) = v;
#pragma unroll
            for (int c = 0; c < 4; c++) { float y = acc[c][j]; ls[c] += y; lq[c] += y*y; }
        }
    }
    __syncthreads();
    *(float4*)&sred[ty][4*tx] = make_float4(ls[0], ls[1], ls[2], ls[3]);
    __syncthreads();
    if (tid < 64) {
        float t = 0.f;
#pragma unroll
        for (int yy = 0; yy < 16; yy++) t += sred[yy][tid];
        atomicAdd(&g_sum2[tid], (double)t);
    }
    __syncthreads();
    *(float4*)&sred[ty][4*tx] = make_float4(lq[0], lq[1], lq[2], lq[3]);
    __syncthreads();
    if (tid < 64) {
        float t = 0.f;
#pragma unroll
        for (int yy = 0; yy < 16; yy++) t += sred[yy][tid];
        atomicAdd(&g_sq2[tid], (double)t);
    }
}

// ---------------- layer 3: 256 threads, acc[4][4], max/min over k ------------
__global__ __launch_bounds__(256, 3) void k_layer3(const float* __restrict__ w,
                                                   const float* __restrict__ bias) {
    __shared__ __align__(16) float sX[32*RS2];
    __shared__ __align__(16) float sWT[64*128];
    __shared__ __align__(16) float sredx[8][128];
    __shared__ __align__(16) float sredn[8][128];
    __shared__ __align__(16) float sa[64], sc[64];
    __shared__ float sb[128];
    const int tid = threadIdx.x;
    if (tid < 64)  { sa[tid] = g_a2[tid]; sc[tid] = g_c2[tid]; }
    if (tid < 128) sb[tid] = bias[tid];
    for (int e = tid; e < 64*128; e += 256) {
        int i = e >> 7, o = e & 127;
        sWT[i*128 + o] = w[o*64 + i];
    }
    __syncthreads();
    const int tx = tid & 31, ty = tid >> 5;      // ch 4*tx+c, rows ty+8j (j<4)
    const float bb0 = sb[4*tx+0], bb1 = sb[4*tx+1], bb2 = sb[4*tx+2], bb3 = sb[4*tx+3];
    float ls[4] = {0,0,0,0}, lq[4] = {0,0,0,0};
    for (int t = 0; t < TILES3; t++) {
        const int grp = blockIdx.x*TILES3 + t;
        const int row0 = grp * 32;
        __syncthreads();
        for (int e = tid; e < 32*16; e += 256) {
            int r = e >> 4, q = e & 15;
            float4 v = *(const float4*)(g_y2 + (size_t)(row0 + r)*64 + q*4);
            float4 A = *(const float4*)(sa + q*4);
            float4 C = *(const float4*)(sc + q*4);
            v.x = fmaxf(fmaf(A.x, v.x, C.x), 0.f);
            v.y = fmaxf(fmaf(A.y, v.y, C.y), 0.f);
            v.z = fmaxf(fmaf(A.z, v.z, C.z), 0.f);
            v.w = fmaxf(fmaf(A.w, v.w, C.w), 0.f);
            *(float4*)(sX + r*RS2 + q*4) = v;
        }
        __syncthreads();
        float acc[4][4];
#pragma unroll
        for (int j = 0; j < 4; j++) { acc[0][j]=bb0; acc[1][j]=bb1; acc[2][j]=bb2; acc[3][j]=bb3; }
#pragma unroll
        for (int i4 = 0; i4 < 16; i4++) {
            float4 w4[4];
#pragma unroll
            for (int ii = 0; ii < 4; ii++)
                w4[ii] = *(const float4*)(sWT + (i4*4+ii)*128 + 4*tx);
#pragma unroll
            for (int j = 0; j < 4; j++) {
                const float4 x4 = *(const float4*)(sX + (ty+8*j)*RS2 + i4*4);
                FMA4(w4[0], x4.x, j); FMA4(w4[1], x4.y, j);
                FMA4(w4[2], x4.z, j); FMA4(w4[3], x4.w, j);
            }
        }
        float lx[4] = {-1e30f,-1e30f,-1e30f,-1e30f};
        float ln[4] = { 1e30f, 1e30f, 1e30f, 1e30f};
#pragma unroll
        for (int c = 0; c < 4; c++)
#pragma unroll
            for (int j = 0; j < 4; j++) {
                float y = acc[c][j];
                ls[c] += y; lq[c] += y*y;
                lx[c] = fmaxf(lx[c], y); ln[c] = fminf(ln[c], y);
            }
        *(float4*)&sredx[ty][4*tx] = make_float4(lx[0], lx[1], lx[2], lx[3]);
        *(float4*)&sredn[ty][4*tx] = make_float4(ln[0], ln[1], ln[2], ln[3]);
        __syncthreads();
        if (tid < 128) {
            float mx = sredx[0][tid], mn = sredn[0][tid];
#pragma unroll
            for (int yy = 1; yy < 8; yy++) {
                mx = fmaxf(mx, sredx[yy][tid]);
                mn = fminf(mn, sredn[yy][tid]);
            }
            g_mx[(size_t)grp*128 + tid] = mx;
            g_mn[(size_t)grp*128 + tid] = mn;
        }
    }
    __syncthreads();
    *(float4*)&sredx[ty][4*tx] = make_float4(ls[0], ls[1], ls[2], ls[3]);
    *(float4*)&sredn[ty][4*tx] = make_float4(lq[0], lq[1], lq[2], lq[3]);
    __syncthreads();
    if (tid < 128) {
        float ts = 0.f, tq = 0.f;
#pragma unroll
        for (int yy = 0; yy < 8; yy++) { ts += sredx[yy][tid]; tq += sredn[yy][tid]; }
        atomicAdd(&g_sum3[tid], (double)ts);
        atomicAdd(&g_sq3[tid], (double)tq);
    }
}

// ---------------- BN parameter derivation ------------------------------------
__global__ void k_bn(int layer, const float* __restrict__ gg,
                     const float* __restrict__ be, int n) {
    int i = threadIdx.x;
    if (i >= n) return;
    const double* sum; const double* sq; float* a; float* c;
    if (layer == 0)      { sum = g_sum1; sq = g_sq1; a = g_a1; c = g_c1; }
    else if (layer == 1) { sum = g_sum2; sq = g_sq2; a = g_a2; c = g_c2; }
    else                 { sum = g_sum3; sq = g_sq3; a = g_a3; c = g_c3; }
    const double invM = 1.0 / (double)M_ROWS;
    double mean = sum[i] * invM;
    double var  = sq[i] * invM - mean * mean;
    double A = (double)gg[i] / sqrt(var + 1e-5);
    a[i] = (float)A;
    c[i] = (float)((double)be[i] - A * mean);
}

// ---------------- final ------------------------------------------------------
__global__ __launch_bounds__(256) void k_final(float* __restrict__ out) {
    int gid = blockIdx.x * 256 + threadIdx.x;
    int s  = gid & 1023;
    int ch = (gid >> 10) & 127;
    int b  = gid >> 17;
    float A = g_a3[ch], C = g_c3[ch];
    size_t gi = ((size_t)((b << 10) | s))*128 + ch;
    float m = (A >= 0.f) ? g_mx[gi] : g_mn[gi];
    out[OUT_XYZ_ELEMS + gid] = fmaxf(fmaf(A, m, C), 0.f);
}

// ---------------- launch -----------------------------------------------------
extern "C" void kernel_launch(void* const* d_in, const int* in_sizes, int n_in,
                              void* d_out, int out_size) {
    const float* xyz    = (const float*)d_in[0];
    const float* points = (const float*)d_in[1];
    const float* w0  = (const float*)d_in[2];
    const float* b0  = (const float*)d_in[3];
    const float* g0  = (const float*)d_in[4];
    const float* be0 = (const float*)d_in[5];
    const float* w1  = (const float*)d_in[6];
    const float* b1  = (const float*)d_in[7];
    const float* g1  = (const float*)d_in[8];
    const float* be1 = (const float*)d_in[9];
    const float* w2  = (const float*)d_in[10];
    const float* b2  = (const float*)d_in[11];
    const float* g2  = (const float*)d_in[12];
    const float* be2 = (const float*)d_in[13];
    float* out = (float*)d_out;
    (void)in_sizes; (void)n_in; (void)out_size;

    const size_t smem_xyz = (size_t)3 * NN * sizeof(float);   // 48KB dynamic
    static int attr_done = 0;
    if (!attr_done) {
        cudaFuncSetAttribute(k_fps, cudaFuncAttributeMaxDynamicSharedMemorySize,
                             (int)smem_xyz);
        cudaFuncSetAttribute(k_ball, cudaFuncAttributeMaxDynamicSharedMemorySize,
                             (int)smem_xyz);
        attr_done = 1;
    }

    k_init<<<1, 128>>>();
    k_fps<<<BB, 512, smem_xyz>>>(xyz, out);
    k_ball<<<dim3(SS/32, BB), 1024, smem_xyz>>>(xyz, out);
    k_layer1<<<1024, 256>>>(xyz, points, out, w0, b0);
    k_bn<<<1, 128>>>(0, g0, be0, 64);
    k_layer2<<<1024, 256>>>(w1, b1);
    k_bn<<<1, 128>>>(1, g1, be1, 64);
    k_layer3<<<1024, 256>>>(w2, b2);
    k_bn<<<1, 128>>>(2, g2, be2, 128);
    k_final<<<(BB*128*SS)/256, 256>>>(out);
}

// round 7
// speedup vs baseline: 2.1837x; 1.0005x over previous
#include <cuda_runtime.h>
#include <cuda_bf16.h>
#include <math.h>
#include <stdint.h>

#define BB 16
#define NN 4096
#define SS 1024
#define KK 32
#define M_ROWS (BB*SS*KK)        // 524288
#define OUT_XYZ_ELEMS (BB*SS*3)

#define RS1 40
#define STR 72    // bf16 row stride for mma smem tiles (144B -> conflict-free frags)

// packed f32x2 helpers (sm_103a-safe, arch-generic)
#define ADD2(o,a,b) asm("add.rn.f32x2 %0,%1,%2;" : "=l"(o) : "l"(a), "l"(b))
#define MUL2(o,a,b) asm("mul.rn.f32x2 %0,%1,%2;" : "=l"(o) : "l"(a), "l"(b))
#define PACK2(o,lo,hi) asm("mov.b64 %0,{%1,%2};" : "=l"(o) : "f"(lo), "f"(hi))
#define UNPACK2(lo,hi,v) asm("mov.b64 {%0,%1},%2;" : "=f"(lo), "=f"(hi) : "l"(v))
#define REDUX_MAX(o,v) asm("redux.sync.max.s32 %0,%1,0xffffffff;" : "=r"(o) : "r"(v))
#define REDUX_MIN(o,v) asm("redux.sync.min.s32 %0,%1,0xffffffff;" : "=r"(o) : "r"(v))
// pack two f32 -> bf16x2 (second arg -> low 16 bits)
#define PACKBF(o, hi, lo) asm("cvt.rn.bf16x2.f32 %0, %1, %2;" : "=r"(o) : "f"(hi), "f"(lo))

// warp-level bf16 MMA (arch-generic sm_80+): D[16x8] += A[16x16] * B[16x8]
__device__ __forceinline__ void mma_bf16(float* d, const uint32_t* a, const uint32_t* b) {
    asm volatile("mma.sync.aligned.m16n8k16.row.col.f32.bf16.bf16.f32 "
        "{%0,%1,%2,%3}, {%4,%5,%6,%7}, {%8,%9}, {%0,%1,%2,%3};"
        : "+f"(d[0]), "+f"(d[1]), "+f"(d[2]), "+f"(d[3])
        : "r"(a[0]), "r"(a[1]), "r"(a[2]), "r"(a[3]), "r"(b[0]), "r"(b[1]));
}

// ---------------- scratch ----------------------------------------------------
__device__ float  g_y1[M_ROWS*64];
__device__ float  g_y2[M_ROWS*64];
__device__ float  g_mx[BB*SS*128];
__device__ float  g_mn[BB*SS*128];
__device__ int    g_ball[M_ROWS];
__device__ double g_sum1[64],  g_sq1[64];
__device__ double g_sum2[64],  g_sq2[64];
__device__ double g_sum3[128], g_sq3[128];
__device__ float  g_a1[64], g_c1[64];
__device__ float  g_a2[64], g_c2[64];
__device__ float  g_a3[128], g_c3[128];

__global__ void k_init() {
    int t = threadIdx.x;
    if (t < 64)  { g_sum1[t]=0.0; g_sq1[t]=0.0; g_sum2[t]=0.0; g_sq2[t]=0.0; }
    if (t < 128) { g_sum3[t]=0.0; g_sq3[t]=0.0; }
}

// ---------------- FPS (unchanged, bit-exact vs reference) --------------------
__global__ __launch_bounds__(512) void k_fps(const float* __restrict__ xyz,
                                             float* __restrict__ newxyz) {
    extern __shared__ float sm[];
    float* sxs = sm; float* sys = sm + NN; float* szs = sm + 2*NN;
    __shared__ float swv[2][16];
    __shared__ int   swi[2][16];
    const int b = blockIdx.x, tid = threadIdx.x;
    const float* base = xyz + (size_t)b*NN*3;
    float pxs[8], pys[8], pzs[8], dist[8];
#pragma unroll
    for (int k = 0; k < 8; k++) {
        const int i = tid + (k << 9);
        float x = base[3*i+0], y = base[3*i+1], z = base[3*i+2];
        pxs[k]=x; pys[k]=y; pzs[k]=z;
        sxs[i]=x; sys[i]=y; szs[i]=z;
        dist[k] = 1e10f;
    }
    unsigned long long px2[4], py2[4], pz2[4];
#pragma unroll
    for (int j = 0; j < 4; j++) {
        PACK2(px2[j], pxs[2*j], pxs[2*j+1]);
        PACK2(py2[j], pys[2*j], pys[2*j+1]);
        PACK2(pz2[j], pzs[2*j], pzs[2*j+1]);
    }
    float* outc = newxyz + (size_t)b*SS*3;
    __syncthreads();
    float ccx = sxs[0], ccy = sys[0], ccz = szs[0];
    if (tid == 0) { outc[0]=ccx; outc[1]=ccy; outc[2]=ccz; }
    const int lane = tid & 31, w = tid >> 5;
    for (int it = 0; it < SS-1; it++) {
        const int pb = it & 1;
        const float ncx = -ccx, ncy = -ccy, ncz = -ccz;
        unsigned long long ncx2, ncy2, ncz2;
        PACK2(ncx2, ncx, ncx); PACK2(ncy2, ncy, ncy); PACK2(ncz2, ncz, ncz);
        float bv = -1.0f;
#pragma unroll
        for (int j = 0; j < 4; j++) {
            unsigned long long dx,dy,dz,qx,qy,qz,s2,d2;
            ADD2(dx, px2[j], ncx2);
            ADD2(dy, py2[j], ncy2);
            ADD2(dz, pz2[j], ncz2);
            MUL2(qx, dx, dx); MUL2(qy, dy, dy); MUL2(qz, dz, dz);
            ADD2(s2, qx, qy); ADD2(d2, s2, qz);
            float d0, d1; UNPACK2(d0, d1, d2);
            dist[2*j]   = fminf(dist[2*j],   d0);
            dist[2*j+1] = fminf(dist[2*j+1], d1);
            bv = fmaxf(bv, dist[2*j]); bv = fmaxf(bv, dist[2*j+1]);
        }
        int bi = 0x7fffffff;
#pragma unroll
        for (int k = 7; k >= 0; k--)
            if (dist[k] == bv) bi = tid + (k << 9);
        int vmax; REDUX_MAX(vmax, __float_as_int(bv));
        int ti = (__float_as_int(bv) == vmax) ? bi : 0x7fffffff;
        int imin; REDUX_MIN(imin, ti);
        if (lane == 0) { swv[pb][w] = __int_as_float(vmax); swi[pb][w] = imin; }
        __syncthreads();
        float v  = (lane < 16) ? swv[pb][lane] : -1.0f;
        int   i2 = (lane < 16) ? swi[pb][lane] : 0x7fffffff;
        int vg; REDUX_MAX(vg, __float_as_int(v));
        int t2 = (__float_as_int(v) == vg) ? i2 : 0x7fffffff;
        int ig; REDUX_MIN(ig, t2);
        ccx = sxs[ig]; ccy = sys[ig]; ccz = szs[ig];
        if (tid == 0) {
            outc[3*(it+1)+0]=ccx; outc[3*(it+1)+1]=ccy; outc[3*(it+1)+2]=ccz;
        }
    }
}

// ---------------- ball query (unchanged) -------------------------------------
__global__ __launch_bounds__(1024) void k_ball(const float* __restrict__ xyz,
                                               const float* __restrict__ newxyz) {
    extern __shared__ float sm[];
    float* sx = sm; float* sy = sm + NN; float* sz = sm + 2*NN;
    const int b = blockIdx.y;
    const float* base = xyz + (size_t)b*NN*3;
    for (int i = threadIdx.x; i < NN; i += 1024) {
        sx[i] = base[3*i+0]; sy[i] = base[3*i+1]; sz[i] = base[3*i+2];
    }
    __syncthreads();
    const int wid = threadIdx.x >> 5, lane = threadIdx.x & 31;
    const int s = blockIdx.x * 32 + wid;
    const int g = b * SS + s;
    const float cx = newxyz[3*g+0], cy = newxyz[3*g+1], cz = newxyz[3*g+2];
    int* out = g_ball + (size_t)g*KK;
    int count = 0, first = -1;
    for (int j0 = 0; j0 < NN && count < KK; j0 += 32) {
        const int j = j0 + lane;
        float dx = sx[j]-cx, dy = sy[j]-cy, dz = sz[j]-cz;
        float d = __fadd_rn(__fadd_rn(__fmul_rn(dx,dx), __fmul_rn(dy,dy)),
                            __fmul_rn(dz,dz));
        const bool in = !(d > 0.04f);
        unsigned m = __ballot_sync(0xffffffffu, in);
        if (first < 0 && m) first = j0 + __ffs(m) - 1;
        int pre = __popc(m & ((1u << lane) - 1u));
        if (in) { int p = count + pre; if (p < KK) out[p] = j; }
        count += __popc(m);
    }
    if (count < KK) {
        for (int t = count + lane; t < KK; t += 32) out[t] = first;
    }
}

#define FMA4(W4, xs, j) \
    acc[0][j] = fmaf((W4).x, (xs), acc[0][j]); \
    acc[1][j] = fmaf((W4).y, (xs), acc[1][j]); \
    acc[2][j] = fmaf((W4).z, (xs), acc[2][j]); \
    acc[3][j] = fmaf((W4).w, (xs), acc[3][j]);

// ---------------- layer 1 (scalar, unchanged) --------------------------------
__global__ __launch_bounds__(256, 4) void k_layer1(const float* __restrict__ xyz,
                                                   const float* __restrict__ points,
                                                   const float* __restrict__ newxyz,
                                                   const float* __restrict__ w,
                                                   const float* __restrict__ bias) {
    __shared__ __align__(16) float sX[64*RS1];
    __shared__ __align__(16) float sWT[36*64];
    __shared__ __align__(16) float sred[16][64];
    __shared__ float sb[64];
    const int tid = threadIdx.x;
    if (tid < 64) sb[tid] = bias[tid];
    for (int e = tid; e < 36*64; e += 256) {
        int i = e >> 6, o = e & 63;
        float v = (i < 32) ? w[o*35 + 3 + i] : ((i < 35) ? w[o*35 + (i-32)] : 0.f);
        sWT[i*64 + o] = v;
    }
    __syncthreads();
    const int tx = tid & 15, ty = tid >> 4;
    const float bb0 = sb[4*tx+0], bb1 = sb[4*tx+1], bb2 = sb[4*tx+2], bb3 = sb[4*tx+3];
    float ls[4] = {0,0,0,0}, lq[4] = {0,0,0,0};
    for (int t = 0; t < 8; t++) {
        const int row0 = (blockIdx.x*8 + t) * 64;
        const int b = row0 >> 15;
        const int grp0 = row0 >> 5;
        __syncthreads();
        {
            const int r = tid >> 2, h = tid & 3;
            const int pidx = g_ball[row0 + r];
            const float4* prow = (const float4*)(points + ((size_t)b*NN + pidx)*32) + h*2;
            float4* dst = (float4*)(sX + r*RS1) + h*2;
            dst[0] = prow[0]; dst[1] = prow[1];
            if (h == 0) {
                const float* pc  = xyz + ((size_t)b*NN + pidx)*3;
                const float* cen = newxyz + (size_t)(grp0 + (r >> 5))*3;
                float4 v;
                v.x = pc[0]-cen[0]; v.y = pc[1]-cen[1]; v.z = pc[2]-cen[2]; v.w = 0.f;
                *(float4*)(sX + r*RS1 + 32) = v;
            }
        }
        __syncthreads();
        float acc[4][4];
#pragma unroll
        for (int j = 0; j < 4; j++) { acc[0][j]=bb0; acc[1][j]=bb1; acc[2][j]=bb2; acc[3][j]=bb3; }
#pragma unroll
        for (int i4 = 0; i4 < 9; i4++) {
            float4 w4[4];
#pragma unroll
            for (int ii = 0; ii < 4; ii++)
                w4[ii] = *(const float4*)(sWT + (i4*4+ii)*64 + 4*tx);
#pragma unroll
            for (int j = 0; j < 4; j++) {
                const float4 x4 = *(const float4*)(sX + (ty+16*j)*RS1 + i4*4);
                FMA4(w4[0], x4.x, j); FMA4(w4[1], x4.y, j);
                FMA4(w4[2], x4.z, j); FMA4(w4[3], x4.w, j);
            }
        }
#pragma unroll
        for (int j = 0; j < 4; j++) {
            float4 v;
            v.x = acc[0][j]; v.y = acc[1][j]; v.z = acc[2][j]; v.w = acc[3][j];
            *(float4*)(g_y1 + (size_t)(row0 + ty + 16*j)*64 + 4*tx) = v;
#pragma unroll
            for (int c = 0; c < 4; c++) { float y = acc[c][j]; ls[c] += y; lq[c] += y*y; }
        }
    }
    __syncthreads();
    *(float4*)&sred[ty][4*tx] = make_float4(ls[0], ls[1], ls[2], ls[3]);
    __syncthreads();
    if (tid < 64) {
        float t = 0.f;
#pragma unroll
        for (int yy = 0; yy < 16; yy++) t += sred[yy][tid];
        atomicAdd(&g_sum1[tid], (double)t);
    }
    __syncthreads();
    *(float4*)&sred[ty][4*tx] = make_float4(lq[0], lq[1], lq[2], lq[3]);
    __syncthreads();
    if (tid < 64) {
        float t = 0.f;
#pragma unroll
        for (int yy = 0; yy < 16; yy++) t += sred[yy][tid];
        atomicAdd(&g_sq1[tid], (double)t);
    }
}

// ---------------- split helper: 8 f32 -> hi/lo bf16x2 quads ------------------
__device__ __forceinline__ void split8(const float* x, uint4& H, uint4& L) {
    uint32_t h01,h23,h45,h67;
    PACKBF(h01, x[1], x[0]); PACKBF(h23, x[3], x[2]);
    PACKBF(h45, x[5], x[4]); PACKBF(h67, x[7], x[6]);
    float r[8];
    r[0] = x[0] - __uint_as_float(h01 << 16);
    r[1] = x[1] - __uint_as_float(h01 & 0xffff0000u);
    r[2] = x[2] - __uint_as_float(h23 << 16);
    r[3] = x[3] - __uint_as_float(h23 & 0xffff0000u);
    r[4] = x[4] - __uint_as_float(h45 << 16);
    r[5] = x[5] - __uint_as_float(h45 & 0xffff0000u);
    r[6] = x[6] - __uint_as_float(h67 << 16);
    r[7] = x[7] - __uint_as_float(h67 & 0xffff0000u);
    uint32_t l01,l23,l45,l67;
    PACKBF(l01, r[1], r[0]); PACKBF(l23, r[3], r[2]);
    PACKBF(l45, r[5], r[4]); PACKBF(l67, r[7], r[6]);
    H.x=h01; H.y=h23; H.z=h45; H.w=h67;
    L.x=l01; L.y=l23; L.z=l45; L.w=l67;
}

// BN+ReLU 8-lane apply
__device__ __forceinline__ void bnrelu8(const float4 a4, const float4 b4,
                                        const float* sa, const float* sc,
                                        int k8, float* x) {
    float4 A0 = *(const float4*)(sa + 8*k8);
    float4 C0 = *(const float4*)(sc + 8*k8);
    float4 A1 = *(const float4*)(sa + 8*k8 + 4);
    float4 C1 = *(const float4*)(sc + 8*k8 + 4);
    x[0] = fmaxf(fmaf(A0.x, a4.x, C0.x), 0.f);
    x[1] = fmaxf(fmaf(A0.y, a4.y, C0.y), 0.f);
    x[2] = fmaxf(fmaf(A0.z, a4.z, C0.z), 0.f);
    x[3] = fmaxf(fmaf(A0.w, a4.w, C0.w), 0.f);
    x[4] = fmaxf(fmaf(A1.x, b4.x, C1.x), 0.f);
    x[5] = fmaxf(fmaf(A1.y, b4.y, C1.y), 0.f);
    x[6] = fmaxf(fmaf(A1.z, b4.z, C1.z), 0.f);
    x[7] = fmaxf(fmaf(A1.w, b4.w, C1.w), 0.f);
}

// ---------------- layer 2: mma.sync bf16-split, BN1+ReLU -> 64 ---------------
// dyn smem: Ah[128][STR] Al[128][STR] Bh[64][STR] Bl[64][STR] (bf16)
__global__ __launch_bounds__(128) void k_layer2m(const float* __restrict__ w,
                                                 const float* __restrict__ bias) {
    extern __shared__ __align__(16) __nv_bfloat16 dsm2[];
    __nv_bfloat16* Ah = dsm2;
    __nv_bfloat16* Al = Ah + 128*STR;
    __nv_bfloat16* Bh = Al + 128*STR;
    __nv_bfloat16* Bl = Bh + 64*STR;
    __shared__ float sa[64], sc[64], sb[64];
    __shared__ float s_sum[64], s_sq[64];
    const int tid = threadIdx.x, wid = tid >> 5, lane = tid & 31;
    const int g = lane >> 2, tg = lane & 3;
    if (tid < 64) { sa[tid]=g_a1[tid]; sc[tid]=g_c1[tid]; sb[tid]=bias[tid];
                    s_sum[tid]=0.f; s_sq[tid]=0.f; }
    for (int e = tid; e < 4096; e += 128) {
        int n = e >> 6, k = e & 63;
        float v = w[e];
        __nv_bfloat16 h = __float2bfloat16_rn(v);
        __nv_bfloat16 l = __float2bfloat16_rn(v - __bfloat162float(h));
        Bh[n*STR + k] = h; Bl[n*STR + k] = l;
    }
    const int wr0 = wid * 32;
    float ls0[8]={0,0,0,0,0,0,0,0}, ls1[8]={0,0,0,0,0,0,0,0};
    float lq0[8]={0,0,0,0,0,0,0,0}, lq1[8]={0,0,0,0,0,0,0,0};
    for (int t = 0; t < 4; t++) {
        const int row0 = (blockIdx.x*4 + t) * 128;
        __syncthreads();
        {   // prologue: thread = row
            const float4* yr = (const float4*)(g_y1 + (size_t)(row0 + tid)*64);
#pragma unroll
            for (int k8 = 0; k8 < 8; k8++) {
                float x[8]; uint4 H, L;
                bnrelu8(yr[2*k8], yr[2*k8+1], sa, sc, k8, x);
                split8(x, H, L);
                *(uint4*)(Ah + tid*STR + k8*8) = H;
                *(uint4*)(Al + tid*STR + k8*8) = L;
            }
        }
        __syncthreads();
        float d[2][8][4];
#pragma unroll
        for (int mt = 0; mt < 2; mt++)
#pragma unroll
            for (int nt = 0; nt < 8; nt++)
#pragma unroll
                for (int q = 0; q < 4; q++) d[mt][nt][q] = 0.f;
#pragma unroll
        for (int pass = 0; pass < 3; pass++) {
            const __nv_bfloat16* Ab = (pass == 2) ? Al : Ah;
            const __nv_bfloat16* Bb = (pass == 1) ? Bl : Bh;
#pragma unroll
            for (int ks = 0; ks < 4; ks++) {
                uint32_t a[2][4];
#pragma unroll
                for (int mt = 0; mt < 2; mt++) {
                    const __nv_bfloat16* ap = Ab + (wr0 + mt*16)*STR + ks*16;
                    a[mt][0] = *(const uint32_t*)(ap + g*STR + 2*tg);
                    a[mt][1] = *(const uint32_t*)(ap + (g+8)*STR + 2*tg);
                    a[mt][2] = *(const uint32_t*)(ap + g*STR + 2*tg + 8);
                    a[mt][3] = *(const uint32_t*)(ap + (g+8)*STR + 2*tg + 8);
                }
#pragma unroll
                for (int nt = 0; nt < 8; nt++) {
                    uint32_t b[2];
                    const __nv_bfloat16* bp = Bb + (nt*8 + g)*STR + ks*16 + 2*tg;
                    b[0] = *(const uint32_t*)(bp);
                    b[1] = *(const uint32_t*)(bp + 8);
                    mma_bf16(d[0][nt], a[0], b);
                    mma_bf16(d[1][nt], a[1], b);
                }
            }
        }
#pragma unroll
        for (int nt = 0; nt < 8; nt++) {
            const float bv0 = sb[nt*8 + 2*tg], bv1 = sb[nt*8 + 2*tg + 1];
#pragma unroll
            for (int mt = 0; mt < 2; mt++) {
                float v0 = d[mt][nt][0] + bv0, v1 = d[mt][nt][1] + bv1;
                float v2 = d[mt][nt][2] + bv0, v3 = d[mt][nt][3] + bv1;
                const size_t r = (size_t)(row0 + wr0 + mt*16 + g);
                *(float2*)(g_y2 + r*64 + nt*8 + 2*tg)     = make_float2(v0, v1);
                *(float2*)(g_y2 + (r+8)*64 + nt*8 + 2*tg) = make_float2(v2, v3);
                ls0[nt] += v0 + v2; ls1[nt] += v1 + v3;
                lq0[nt] += v0*v0 + v2*v2; lq1[nt] += v1*v1 + v3*v3;
            }
        }
    }
#pragma unroll
    for (int nt = 0; nt < 8; nt++) {
        atomicAdd(&s_sum[nt*8 + 2*tg],     ls0[nt]);
        atomicAdd(&s_sum[nt*8 + 2*tg + 1], ls1[nt]);
        atomicAdd(&s_sq [nt*8 + 2*tg],     lq0[nt]);
        atomicAdd(&s_sq [nt*8 + 2*tg + 1], lq1[nt]);
    }
    __syncthreads();
    if (tid < 64) {
        atomicAdd(&g_sum2[tid], (double)s_sum[tid]);
        atomicAdd(&g_sq2[tid],  (double)s_sq[tid]);
    }
}

// ---------------- layer 3: mma.sync bf16-split, BN2+ReLU -> 128, max/min -----
// dyn smem: Ah/Al[128][STR], Bh/Bl[128][STR] (bf16). Warp w of tile = group.
__global__ __launch_bounds__(128) void k_layer3m(const float* __restrict__ w,
                                                 const float* __restrict__ bias) {
    extern __shared__ __align__(16) __nv_bfloat16 dsm3[];
    __nv_bfloat16* Ah = dsm3;
    __nv_bfloat16* Al = Ah + 128*STR;
    __nv_bfloat16* Bh = Al + 128*STR;
    __nv_bfloat16* Bl = Bh + 128*STR;
    __shared__ float sa[64], sc[64], sb[128];
    __shared__ float s_sum[128], s_sq[128];
    const int tid = threadIdx.x, wid = tid >> 5, lane = tid & 31;
    const int g = lane >> 2, tg = lane & 3;
    if (tid < 64)  { sa[tid]=g_a2[tid]; sc[tid]=g_c2[tid]; }
    if (tid < 128) { sb[tid]=bias[tid]; s_sum[tid]=0.f; s_sq[tid]=0.f; }
    for (int e = tid; e < 8192; e += 128) {
        int n = e >> 6, k = e & 63;
        float v = w[e];
        __nv_bfloat16 h = __float2bfloat16_rn(v);
        __nv_bfloat16 l = __float2bfloat16_rn(v - __bfloat162float(h));
        Bh[n*STR + k] = h; Bl[n*STR + k] = l;
    }
    const int wr0 = wid * 32;
    for (int t = 0; t < 4; t++) {
        const int row0 = (blockIdx.x*4 + t) * 128;
        const int grp = (row0 >> 5) + wid;   // this warp's 32-row group
        __syncthreads();
        {
            const float4* yr = (const float4*)(g_y2 + (size_t)(row0 + tid)*64);
#pragma unroll
            for (int k8 = 0; k8 < 8; k8++) {
                float x[8]; uint4 H, L;
                bnrelu8(yr[2*k8], yr[2*k8+1], sa, sc, k8, x);
                split8(x, H, L);
                *(uint4*)(Ah + tid*STR + k8*8) = H;
                *(uint4*)(Al + tid*STR + k8*8) = L;
            }
        }
        __syncthreads();
#pragma unroll
        for (int nh = 0; nh < 2; nh++) {
            float d[2][8][4];
#pragma unroll
            for (int mt = 0; mt < 2; mt++)
#pragma unroll
                for (int nt = 0; nt < 8; nt++)
#pragma unroll
                    for (int q = 0; q < 4; q++) d[mt][nt][q] = 0.f;
#pragma unroll
            for (int pass = 0; pass < 3; pass++) {
                const __nv_bfloat16* Ab = (pass == 2) ? Al : Ah;
                const __nv_bfloat16* Bb = (pass == 1) ? Bl : Bh;
#pragma unroll
                for (int ks = 0; ks < 4; ks++) {
                    uint32_t a[2][4];
#pragma unroll
                    for (int mt = 0; mt < 2; mt++) {
                        const __nv_bfloat16* ap = Ab + (wr0 + mt*16)*STR + ks*16;
                        a[mt][0] = *(const uint32_t*)(ap + g*STR + 2*tg);
                        a[mt][1] = *(const uint32_t*)(ap + (g+8)*STR + 2*tg);
                        a[mt][2] = *(const uint32_t*)(ap + g*STR + 2*tg + 8);
                        a[mt][3] = *(const uint32_t*)(ap + (g+8)*STR + 2*tg + 8);
                    }
#pragma unroll
                    for (int nt = 0; nt < 8; nt++) {
                        uint32_t b[2];
                        const __nv_bfloat16* bp = Bb + (nh*64 + nt*8 + g)*STR + ks*16 + 2*tg;
                        b[0] = *(const uint32_t*)(bp);
                        b[1] = *(const uint32_t*)(bp + 8);
                        mma_bf16(d[0][nt], a[0], b);
                        mma_bf16(d[1][nt], a[1], b);
                    }
                }
            }
            // epilogue: per-channel stats + group max/min (warp == group)
#pragma unroll
            for (int nt = 0; nt < 8; nt++) {
                const int ch0 = nh*64 + nt*8 + 2*tg;
                const float bv0 = sb[ch0], bv1 = sb[ch0 + 1];
                float v00 = d[0][nt][0]+bv0, v01 = d[0][nt][1]+bv1;
                float v02 = d[0][nt][2]+bv0, v03 = d[0][nt][3]+bv1;
                float v10 = d[1][nt][0]+bv0, v11 = d[1][nt][1]+bv1;
                float v12 = d[1][nt][2]+bv0, v13 = d[1][nt][3]+bv1;
                float mx0 = fmaxf(fmaxf(v00,v02), fmaxf(v10,v12));
                float mx1 = fmaxf(fmaxf(v01,v03), fmaxf(v11,v13));
                float mn0 = fminf(fminf(v00,v02), fminf(v10,v12));
                float mn1 = fminf(fminf(v01,v03), fminf(v11,v13));
                float s0 = v00+v02+v10+v12, s1 = v01+v03+v11+v13;
                float q0 = v00*v00+v02*v02+v10*v10+v12*v12;
                float q1 = v01*v01+v03*v03+v11*v11+v13*v13;
#pragma unroll
                for (int off = 16; off >= 4; off >>= 1) {
                    mx0 = fmaxf(mx0, __shfl_down_sync(0xffffffffu, mx0, off));
                    mx1 = fmaxf(mx1, __shfl_down_sync(0xffffffffu, mx1, off));
                    mn0 = fminf(mn0, __shfl_down_sync(0xffffffffu, mn0, off));
                    mn1 = fminf(mn1, __shfl_down_sync(0xffffffffu, mn1, off));
                    s0 += __shfl_down_sync(0xffffffffu, s0, off);
                    s1 += __shfl_down_sync(0xffffffffu, s1, off);
                    q0 += __shfl_down_sync(0xffffffffu, q0, off);
                    q1 += __shfl_down_sync(0xffffffffu, q1, off);
                }
                if (g == 0) {
                    g_mx[(size_t)grp*128 + ch0]     = mx0;
                    g_mx[(size_t)grp*128 + ch0 + 1] = mx1;
                    g_mn[(size_t)grp*128 + ch0]     = mn0;
                    g_mn[(size_t)grp*128 + ch0 + 1] = mn1;
                    atomicAdd(&s_sum[ch0],     s0);
                    atomicAdd(&s_sum[ch0 + 1], s1);
                    atomicAdd(&s_sq [ch0],     q0);
                    atomicAdd(&s_sq [ch0 + 1], q1);
                }
            }
        }
    }
    __syncthreads();
    if (tid < 128) {
        atomicAdd(&g_sum3[tid], (double)s_sum[tid]);
        atomicAdd(&g_sq3[tid],  (double)s_sq[tid]);
    }
}

// ---------------- BN parameter derivation ------------------------------------
__global__ void k_bn(int layer, const float* __restrict__ gg,
                     const float* __restrict__ be, int n) {
    int i = threadIdx.x;
    if (i >= n) return;
    const double* sum; const double* sq; float* a; float* c;
    if (layer == 0)      { sum = g_sum1; sq = g_sq1; a = g_a1; c = g_c1; }
    else if (layer == 1) { sum = g_sum2; sq = g_sq2; a = g_a2; c = g_c2; }
    else                 { sum = g_sum3; sq = g_sq3; a = g_a3; c = g_c3; }
    const double invM = 1.0 / (double)M_ROWS;
    double mean = sum[i] * invM;
    double var  = sq[i] * invM - mean * mean;
    double A = (double)gg[i] / sqrt(var + 1e-5);
    a[i] = (float)A;
    c[i] = (float)((double)be[i] - A * mean);
}

// ---------------- final ------------------------------------------------------
__global__ __launch_bounds__(256) void k_final(float* __restrict__ out) {
    int gid = blockIdx.x * 256 + threadIdx.x;
    int s  = gid & 1023;
    int ch = (gid >> 10) & 127;
    int b  = gid >> 17;
    float A = g_a3[ch], C = g_c3[ch];
    size_t gi = ((size_t)((b << 10) | s))*128 + ch;
    float m = (A >= 0.f) ? g_mx[gi] : g_mn[gi];
    out[OUT_XYZ_ELEMS + gid] = fmaxf(fmaf(A, m, C), 0.f);
}

// ---------------- launch -----------------------------------------------------
extern "C" void kernel_launch(void* const* d_in, const int* in_sizes, int n_in,
                              void* d_out, int out_size) {
    const float* xyz    = (const float*)d_in[0];
    const float* points = (const float*)d_in[1];
    const float* w0  = (const float*)d_in[2];
    const float* b0  = (const float*)d_in[3];
    const float* g0  = (const float*)d_in[4];
    const float* be0 = (const float*)d_in[5];
    const float* w1  = (const float*)d_in[6];
    const float* b1  = (const float*)d_in[7];
    const float* g1  = (const float*)d_in[8];
    const float* be1 = (const float*)d_in[9];
    const float* w2  = (const float*)d_in[10];
    const float* b2  = (const float*)d_in[11];
    const float* g2  = (const float*)d_in[12];
    const float* be2 = (const float*)d_in[13];
    float* out = (float*)d_out;
    (void)in_sizes; (void)n_in; (void)out_size;

    const size_t smem_xyz = (size_t)3 * NN * sizeof(float);      // 48KB
    const size_t smem_l2  = (size_t)(2*128*STR + 2*64*STR) * 2;  // 55296B
    const size_t smem_l3  = (size_t)(2*128*STR + 2*128*STR) * 2; // 73728B
    static int attr_done = 0;
    if (!attr_done) {
        cudaFuncSetAttribute(k_fps,  cudaFuncAttributeMaxDynamicSharedMemorySize, (int)smem_xyz);
        cudaFuncSetAttribute(k_ball, cudaFuncAttributeMaxDynamicSharedMemorySize, (int)smem_xyz);
        cudaFuncSetAttribute(k_layer2m, cudaFuncAttributeMaxDynamicSharedMemorySize, (int)smem_l2);
        cudaFuncSetAttribute(k_layer3m, cudaFuncAttributeMaxDynamicSharedMemorySize, (int)smem_l3);
        attr_done = 1;
    }

    k_init<<<1, 128>>>();
    k_fps<<<BB, 512, smem_xyz>>>(xyz, out);
    k_ball<<<dim3(SS/32, BB), 1024, smem_xyz>>>(xyz, out);
    k_layer1<<<1024, 256>>>(xyz, points, out, w0, b0);
    k_bn<<<1, 128>>>(0, g0, be0, 64);
    k_layer2m<<<1024, 128, smem_l2>>>(w1, b1);
    k_bn<<<1, 128>>>(1, g1, be1, 64);
    k_layer3m<<<1024, 128, smem_l3>>>(w2, b2);
    k_bn<<<1, 128>>>(2, g2, be2, 128);
    k_final<<<(BB*128*SS)/256, 256>>>(out);
}